// round 14
// baseline (speedup 1.0000x reference)
#include <cuda_runtime.h>
#include <cuda_fp16.h>
#include <cstdint>

#define NB  8
#define CHN 256
#define HW  25600
#define DD  512
#define NN  1600
#define NNP 1664

// ---------------- scratch (__device__ globals; allocation-free) ------------
__device__ float g_sc[NB*DD*DD];    // scores fp32 [d][e']
__device__ __align__(128) __half g_oph[NB*DD*NN];     // attn@V output fp16 [d][n]
__device__ __align__(128) __half g_fq_hi[NB*DD*NN];   // [d][n] single plane
__device__ __align__(128) __half g_fk_hi[NB*DD*NN];   // [e'][n] single plane
__device__ __align__(128) __half g_fvT_hi[NB*NNP*DD]; // [n][e'] single plane
__device__ __align__(128) __half g_at_hi[NB*DD*DD];   // [d][e'] single plane
__device__ __align__(128) __half g_w_hi[96*256];      // qkv weights single plane
__device__ __align__(128) __half g_wu_hi[256*32];     // Wu fp16 hi/mi planes
__device__ __align__(128) __half g_wu_mi[256*32];

typedef unsigned long long u64;

// ---------------- PTX helpers (baseline ISA only) ---------------------------
__device__ __forceinline__ uint32_t smem_u32(const void* p) {
    uint32_t a;
    asm("{ .reg .u64 t; cvta.to.shared.u64 t, %1; cvt.u32.u64 %0, t; }" : "=r"(a) : "l"(p));
    return a;
}
__device__ __forceinline__ void cpa16(uint32_t s, const void* g) {
    asm volatile("cp.async.cg.shared.global [%0], [%1], 16;" :: "r"(s), "l"(g));
}
#define CPA_COMMIT() asm volatile("cp.async.commit_group;" ::: "memory")

__device__ __forceinline__ void ldsm4(uint32_t* r, uint32_t a) {
    asm volatile("ldmatrix.sync.aligned.m8n8.x4.shared.b16 {%0,%1,%2,%3}, [%4];"
        : "=r"(r[0]), "=r"(r[1]), "=r"(r[2]), "=r"(r[3]) : "r"(a));
}
__device__ __forceinline__ void ldsm4t(uint32_t* r, uint32_t a) {
    asm volatile("ldmatrix.sync.aligned.m8n8.x4.trans.shared.b16 {%0,%1,%2,%3}, [%4];"
        : "=r"(r[0]), "=r"(r[1]), "=r"(r[2]), "=r"(r[3]) : "r"(a));
}
__device__ __forceinline__ void ldsm2t(uint32_t* r, uint32_t a) {
    asm volatile("ldmatrix.sync.aligned.m8n8.x2.trans.shared.b16 {%0,%1}, [%2];"
        : "=r"(r[0]), "=r"(r[1]) : "r"(a));
}
__device__ __forceinline__ void mma_f16(float* d, const uint32_t* a, uint32_t b0, uint32_t b1) {
    asm volatile(
        "mma.sync.aligned.m16n8k16.row.col.f32.f16.f16.f32 "
        "{%0,%1,%2,%3},{%4,%5,%6,%7},{%8,%9},{%0,%1,%2,%3};"
        : "+f"(d[0]), "+f"(d[1]), "+f"(d[2]), "+f"(d[3])
        : "r"(a[0]), "r"(a[1]), "r"(a[2]), "r"(a[3]), "r"(b0), "r"(b1));
}

// pack 2 floats -> fp16x2 (lo=a, hi=b)
__device__ __forceinline__ uint32_t pack_h2(float a, float b) {
    uint32_t r;
    asm("cvt.rn.f16x2.f32 %0, %1, %2;" : "=r"(r) : "f"(b), "f"(a));
    return r;
}

// ---------------------------------------------------------------------------
// K-1: W q/v/k rows -> single fp16 plane; Wu -> fp16 hi/mi planes.
// ---------------------------------------------------------------------------
__global__ __launch_bounds__(256) void k_wsplit(
    const float* __restrict__ Wq, const float* __restrict__ Wv, const float* __restrict__ Wk,
    const float* __restrict__ Wu)
{
    int i = blockIdx.x * 256 + threadIdx.x;
    if (i < 96*256) {
        int r = i >> 8, kk = i & 255;
        float v = (r < 32) ? Wq[r*256 + kk] : ((r < 64) ? Wv[(r-32)*256 + kk] : Wk[(r-64)*256 + kk]);
        g_w_hi[i] = __float2half_rn(v);
    }
    if (i < 256*32) {
        float v = Wu[i];
        __half h = __float2half_rn(v);
        g_wu_hi[i] = h;
        g_wu_mi[i] = __float2half_rn(v - __half2float(h));
    }
}

// ---------------------------------------------------------------------------
// K1: PERSISTENT tensor-core fused q/k/v 1x1 conv + pixel_unshuffle.
// (exact round-11 champion version)
// ---------------------------------------------------------------------------
__global__ __launch_bounds__(384, 1) void k_projT(
    const float* __restrict__ rgb, const float* __restrict__ depth,
    const float* __restrict__ bq, const float* __restrict__ bk,
    const float* __restrict__ bv)
{
    extern __shared__ __align__(1024) char sm[];
    const int t = threadIdx.x, lane = t & 31, wid = t >> 5;
    const int wn = wid & 3, wm = wid >> 2;       // wm 0..2, wn 0..3
    const uint32_t su = smem_u32(sm);
    const uint32_t XB = su + 49152;
    float* const epi = (float*)(sm + 49152);

    // ---- W plane into smem (once per CTA) ----
    for (int i = t; i < 96*32; i += 384) {
        int m = i >> 5, c = i & 31;
        uint4 v1 = *(const uint4*)((const char*)g_w_hi + m*512 + c*16);
        int sw = (c ^ (m & 7)) * 16;
        *(uint4*)(sm + m*512 + sw) = v1;
    }

    float bias_v[2][2];
#pragma unroll
    for (int mt = 0; mt < 2; mt++)
#pragma unroll
        for (int hh = 0; hh < 2; hh++) {
            int r = wm*32 + mt*16 + (lane >> 2) + hh*8;
            bias_v[mt][hh] = (r < 32) ? bq[r] : ((r < 64) ? bv[r-32] : bk[r-64]);
        }

    int cin_[7], c4_[7], pl_[7];
    bool val_[7];
#pragma unroll
    for (int j = 0; j < 7; j++) {
        int item = t + j*384;
        val_[j] = item < 2560;
        int it2 = val_[j] ? item : 0;
        int src = (it2 >= 1280) ? 1 : 0;
        int rem = it2 - src*1280;
        cin_[j] = rem / 40; c4_[j] = rem % 40;
        pl_[j]  = src ? 12288 : 0;
    }
    __syncthreads();

    const int cta = blockIdx.x;
    int u        = (1280 * cta) / 148;
    const int u1 = (1280 * (cta + 1)) / 148;

    int b = u / 160, h = u - b*160;
    const float* db = depth + (size_t)b*CHN*HW;
    const float* rb = rgb   + (size_t)b*CHN*HW;
    size_t rowoff = (size_t)h * 160;

    float4 rv[7];
    auto ldg_chunk = [&](int c, const float* dB, const float* rB, size_t ro) {
#pragma unroll
        for (int j = 0; j < 7; j++) {
            if (val_[j]) {
                const float* bp = pl_[j] ? rB : dB;
                rv[j] = *(const float4*)(bp + (size_t)(c*32 + cin_[j])*HW + ro + c4_[j]*4);
            }
        }
    };
    auto sts_chunk = [&](int s) {
        const int soff = 49152 + s*24576;
#pragma unroll
        for (int j = 0; j < 7; j++) {
            if (val_[j]) {
                int row = cin_[j], c4 = c4_[j];
                int a = soff + pl_[j] + row*384 + (((c4 >> 1) ^ (row & 7)) * 16) + (c4 & 1)*8;
                uint32_t h01 = pack_h2(rv[j].x, rv[j].y);
                uint32_t h23 = pack_h2(rv[j].z, rv[j].w);
                *(uint2*)(sm + a) = make_uint2(h01, h23);
            }
        }
    };

    ldg_chunk(0, db, rb, rowoff);

    for (; u < u1; u++) {
        const int ip = h & 3, hn = h >> 2, curb = b;

        int nb = b, nh = h + 1;
        if (nh == 160) { nh = 0; nb = b + 1; }
        const bool has_next = (u + 1 < u1);
        const float* ndb = depth + (size_t)nb*CHN*HW;
        const float* nrb = rgb   + (size_t)nb*CHN*HW;
        const size_t nro = (size_t)nh * 160;

        sts_chunk(0);
        ldg_chunk(1, db, rb, rowoff);

        float acc[2][5][4];
#pragma unroll
        for (int i = 0; i < 2; i++)
#pragma unroll
            for (int j = 0; j < 5; j++)
#pragma unroll
                for (int r = 0; r < 4; r++) acc[i][j][r] = 0.0f;

        const int pls = (wm == 2) ? 12288 : 0;

        for (int c = 0; c < 8; c++) {
            __syncthreads();
            if (c + 1 < 8) sts_chunk((c + 1) & 1);
            if (c + 2 < 8)                    ldg_chunk(c + 2, db, rb, rowoff);
            else if (c == 6 && has_next)      ldg_chunk(0, ndb, nrb, nro);
            __syncthreads();

            const uint32_t xs = XB + (c & 1)*24576;
#pragma unroll
            for (int kk = 0; kk < 2; kk++) {
                uint32_t ah[2][4];
#pragma unroll
                for (int mt = 0; mt < 2; mt++) {
                    int m = wm*32 + mt*16 + (lane & 15);
                    int ca = c*4 + kk*2 + (lane >> 4);
                    uint32_t addr = su + m*512 + (ca ^ (m & 7))*16;
                    ldsm4(ah[mt], addr);
                }
                const int krow = kk*16 + (lane & 15);
                const int swz = krow & 7;
                const uint32_t rbase_a = xs + pls + krow*384;
                uint32_t bh[2][4], bh2[2];
#pragma unroll
                for (int tt = 0; tt < 2; tt++) {
                    int cc = wn*5 + tt*2 + (lane >> 4);
                    ldsm4t(bh[tt], rbase_a + (cc ^ swz)*16);
                }
                {
                    int cc = wn*5 + 4;
                    ldsm2t(bh2, rbase_a + (cc ^ swz)*16);
                }
#pragma unroll
                for (int mt = 0; mt < 2; mt++) {
#pragma unroll
                    for (int nt = 0; nt < 5; nt++) {
                        uint32_t b0, b1;
                        if (nt < 4) {
                            int g = nt >> 1, hf = nt & 1;
                            b0 = bh[g][hf*2]; b1 = bh[g][hf*2+1];
                        } else {
                            b0 = bh2[0]; b1 = bh2[1];
                        }
                        mma_f16(acc[mt][nt], ah[mt], b0, b1);
                    }
                }
            }
        }

        __syncthreads();
#pragma unroll
        for (int mt = 0; mt < 2; mt++) {
#pragma unroll
            for (int nt = 0; nt < 5; nt++) {
                int col0 = wn*40 + nt*8 + (lane & 3)*2;
                int nw = col0 >> 2, j0 = col0 & 3;
#pragma unroll
                for (int hh = 0; hh < 2; hh++) {
                    int r = wm*32 + mt*16 + (lane >> 2) + hh*8;
                    epi[(j0*96 + r)*42 + nw]     = acc[mt][nt][hh*2]   + bias_v[mt][hh];
                    epi[((j0+1)*96 + r)*42 + nw] = acc[mt][nt][hh*2+1] + bias_v[mt][hh];
                }
            }
        }
        __syncthreads();

        for (int tk = wid; tk < 416; tk += 12) {
            if (tk < 256) {
                if (lane < 20) {
                    int rr = tk >> 2, j = tk & 3;
                    int row = (rr < 32) ? rr : rr + 32;
                    float2 v = *(const float2*)&epi[(j*96 + row)*42 + lane*2];
                    uint32_t hi = pack_h2(v.x, v.y);
                    int dd = (rr < 32) ? (rr*16 + ip*4 + j)
                                       : ((ip*4 + j)*32 + (rr - 32));
                    size_t base = ((size_t)(curb*DD + dd))*NN + hn*40 + lane*2;
                    __half* dh = (rr < 32) ? g_fq_hi : g_fk_hi;
                    *(uint32_t*)(dh + base) = hi;
                }
            } else {
                if (lane < 16) {
                    int tv = tk - 256;
                    int nw = tv >> 2, j = tv & 3;
                    float v0 = epi[(j*96 + 32 + lane*2)*42 + nw];
                    float v1 = epi[(j*96 + 33 + lane*2)*42 + nw];
                    uint32_t hi = pack_h2(v0, v1);
                    int n = hn*40 + nw;
                    size_t base = ((size_t)curb*NNP + n)*DD + (ip*4 + j)*32 + lane*2;
                    *(uint32_t*)(g_fvT_hi + base) = hi;
                }
            }
        }
        __syncthreads();

        b = nb; h = nh; db = ndb; rb = nrb; rowoff = nro;
    }
}

// ---------------------------------------------------------------------------
// Generic 128x64-tile mma.sync single-pass fp16 GEMM — 3 CTAs/SM:
// __launch_bounds__(256, 3), 3 stages (73728B), prefetch distance 2 issued
// right after the barrier (stage (c+2)%3 fully consumed at iter c-1 -> safe).
// MODE 0: scores (A=fq_hi, B=fk_hi, K=1600, C=g_sc fp32 [512x512])
// MODE 1: attn@V (A=at_hi, B=fvT_hi, K=512, C=g_oph fp16 [512x1600])
// ---------------------------------------------------------------------------
template<int MODE>
__global__ __launch_bounds__(256, 3) void k_gemm()
{
    constexpr int K    = (MODE == 0) ? 1600 : 512;
    constexpr int LD   = (MODE == 0) ? 1600 : 512;
    constexpr int LDC  = (MODE == 0) ? 512  : 1600;
    constexpr long SA  = (MODE == 0) ? (long)DD*NN : (long)DD*DD;
    constexpr long SB  = (MODE == 0) ? (long)DD*NN : (long)NNP*DD;
    constexpr int NCH  = K / 64;

    extern __shared__ __align__(1024) char dsm[];

    const int b  = blockIdx.z;
    const int m0 = blockIdx.y * 128;
    const int n0 = blockIdx.x * 64;
    const int t    = threadIdx.x;
    const int lane = t & 31;
    const int wid  = t >> 5;
    const int wm   = wid & 3;
    const int wn   = wid >> 2;

    const uint32_t smem_u = smem_u32(dsm);

    const __half* Ahi = (MODE == 0 ? g_fq_hi : g_at_hi)  + b*SA + (long)m0*LD;
    const __half* Bhi = (MODE == 0 ? g_fk_hi : g_fvT_hi) + b*SB + (long)n0*LD;

    auto load_stage = [&](int s, int kc) {
        uint32_t base = smem_u + s*24576;
#pragma unroll
        for (int ii = 0; ii < 4; ii++) {
            int i = t + ii*256;
            int row = i >> 3, seg = i & 7;
            uint32_t off = row*128 + seg*16;
            uint32_t sw  = off ^ ((off >> 3) & 0x70);
            long go = (long)row*LD + kc;
            cpa16(base + sw, (const char*)(Ahi + go) + seg*16);
        }
#pragma unroll
        for (int ii = 0; ii < 2; ii++) {
            int i = t + ii*256;
            int row = i >> 3, seg = i & 7;
            uint32_t off = row*128 + seg*16;
            uint32_t sw  = off ^ ((off >> 3) & 0x70);
            long go = (long)row*LD + kc;
            cpa16(base + 16384 + sw, (const char*)(Bhi + go) + seg*16);
        }
        CPA_COMMIT();
    };

    float acc[2][4][4];
#pragma unroll
    for (int i = 0; i < 2; i++)
#pragma unroll
        for (int j = 0; j < 4; j++)
#pragma unroll
            for (int r = 0; r < 4; r++) acc[i][j][r] = 0.0f;

    load_stage(0, 0);
    load_stage(1, 64);

    const int lr = lane & 15;
    const int lc = lane >> 4;

    for (int c = 0; c < NCH; c++) {
        const int s = c - (c/3)*3;
        if (c + 1 < NCH) asm volatile("cp.async.wait_group 1;" ::: "memory");
        else             asm volatile("cp.async.wait_group 0;" ::: "memory");
        __syncthreads();
        if (c + 2 < NCH) {
            int ns = (c + 2) - ((c + 2)/3)*3;
            load_stage(ns, (c + 2)*64);
        }

        const uint32_t base = smem_u + s*24576;
#pragma unroll
        for (int kk = 0; kk < 4; kk++) {
            uint32_t a_hi[2][4];
#pragma unroll
            for (int mt = 0; mt < 2; mt++) {
                int row = wm*32 + mt*16 + lr;
                uint32_t off = row*128 + kk*32 + lc*16;
                uint32_t sw  = off ^ ((off >> 3) & 0x70);
                ldsm4(a_hi[mt], base + sw);
            }
            uint32_t b_hi[2][4];
#pragma unroll
            for (int bt = 0; bt < 2; bt++) {
                int row = wn*32 + bt*16 + lr;
                uint32_t off = row*128 + kk*32 + lc*16;
                uint32_t sw  = off ^ ((off >> 3) & 0x70);
                ldsm4(b_hi[bt], base + 16384 + sw);
            }
#pragma unroll
            for (int mt = 0; mt < 2; mt++) {
#pragma unroll
                for (int nt = 0; nt < 4; nt++) {
                    int bt = nt >> 1, hf = nt & 1;
                    mma_f16(acc[mt][nt], a_hi[mt], b_hi[bt][hf], b_hi[bt][hf+2]);
                }
            }
        }
    }

    const int rq = lane >> 2;
    const int cq = (lane & 3) * 2;
#pragma unroll
    for (int mt = 0; mt < 2; mt++) {
#pragma unroll
        for (int nt = 0; nt < 4; nt++) {
            int col = n0 + wn*32 + nt*8 + cq;
            int row = m0 + wm*32 + mt*16 + rq;
            if (MODE == 0) {
                float* p0 = g_sc + (long)b*DD*DD + (long)row*LDC + col;
                *(float2*)p0            = make_float2(acc[mt][nt][0], acc[mt][nt][1]);
                *(float2*)(p0 + 8L*LDC) = make_float2(acc[mt][nt][2], acc[mt][nt][3]);
            } else {
                __half* p0 = g_oph + (long)b*DD*NN + (long)row*LDC + col;
                *(uint32_t*)p0            = pack_h2(acc[mt][nt][0], acc[mt][nt][1]);
                *(uint32_t*)(p0 + 8L*LDC) = pack_h2(acc[mt][nt][2], acc[mt][nt][3]);
            }
        }
    }
}

// ---------------------------------------------------------------------------
// K3: softmax over rows of g_sc, writes attn as single fp16 plane.
// (exact round-11 version)
// ---------------------------------------------------------------------------
__global__ __launch_bounds__(128) void k_softmax()
{
    __shared__ float red[8];
    const size_t row = blockIdx.x;
    const float* s = g_sc + row * DD;
    const int t = threadIdx.x;

    float v0 = s[t], v1 = s[t+128], v2 = s[t+256], v3 = s[t+384];
    float m = fmaxf(fmaxf(v0, v1), fmaxf(v2, v3));
#pragma unroll
    for (int o = 16; o; o >>= 1) m = fmaxf(m, __shfl_xor_sync(0xffffffffu, m, o));
    if ((t & 31) == 0) red[t >> 5] = m;
    __syncthreads();
    m = fmaxf(fmaxf(red[0], red[1]), fmaxf(red[2], red[3]));

    const float inv = 0.04419417382415922f;  // 1/sqrt(512)
    float e0 = __expf((v0 - m) * inv);
    float e1 = __expf((v1 - m) * inv);
    float e2 = __expf((v2 - m) * inv);
    float e3 = __expf((v3 - m) * inv);
    float sum = e0 + e1 + e2 + e3;
#pragma unroll
    for (int o = 16; o; o >>= 1) sum += __shfl_xor_sync(0xffffffffu, sum, o);
    if ((t & 31) == 0) red[4 + (t >> 5)] = sum;
    __syncthreads();
    float r = 1.0f / (red[4] + red[5] + red[6] + red[7]);

    size_t base = row * DD;
    g_at_hi[base + t]       = __float2half_rn(e0 * r);
    g_at_hi[base + t + 128] = __float2half_rn(e1 * r);
    g_at_hi[base + t + 256] = __float2half_rn(e2 * r);
    g_at_hi[base + t + 384] = __float2half_rn(e3 * r);
}

// ---------------------------------------------------------------------------
// K5: PERSISTENT pixel_shuffle gather + final 1x1 conv (32 -> 256).
// fp16 2-pass: Wu (hi/mi planes from wsplit) x op (1 fp16 plane).
// (exact round-11 version)
// ---------------------------------------------------------------------------
__global__ __launch_bounds__(256, 2) void k_final(
    const float* __restrict__ bu, float* __restrict__ out)
{
    extern __shared__ __align__(1024) char sm[];
    const uint32_t su = smem_u32(sm);
    const int t = threadIdx.x, lane = t & 31, wid = t >> 5;
    const int wm = wid & 3, wn = wid >> 2;
    const int rq = lane >> 2, cq = (lane & 3) * 2;

    {
        const uint4* src_h = (const uint4*)((const char*)g_wu_hi + t*64);
        const uint4* src_m = (const uint4*)((const char*)g_wu_mi + t*64);
#pragma unroll
        for (int c = 0; c < 4; c++) {
            *(uint4*)(sm + t*80 + c*16)         = src_h[c];
            *(uint4*)(sm + 20480 + t*80 + c*16) = src_m[c];
        }
    }

    float bb[4][2];
#pragma unroll
    for (int mt = 0; mt < 4; mt++) {
        int ch0 = wm*64 + mt*16 + rq;
        bb[mt][0] = bu[ch0];
        bb[mt][1] = bu[ch0 + 8];
    }

    const int gc = t >> 3;
    const int ii = (t >> 2) & 1;
    const int gj = t & 3;

    const int cta = blockIdx.x;
    int u        = (3200 * cta) / 296;
    const int u1 = (3200 * (cta + 1)) / 296;

    uint4 hv;
    auto prefetch = [&](int uu) {
        int pb = uu / 400, r = uu - pb*400;
        int php = r / 5, pwb = r - (r/5)*5;
        int i0 = (2*php) & 3, hn = php >> 1;
        int d  = gc*16 + (i0 + ii)*4 + gj;
        hv = *(const uint4*)(g_oph + ((size_t)(pb*DD + d))*NN + hn*40 + pwb*8);
    };
    if (u < u1) prefetch(u);

    for (; u < u1; u++) {
        const int s = u & 1;
        const int b = u / 400, r = u - b*400;
        const int hp = r / 5, wblk = r - (r/5)*5;

        __syncthreads();

        {
            const __half* hvals = (const __half*)&hv;
#pragma unroll
            for (int nw = 0; nw < 8; nw++) {
                int px = ii*32 + nw*4 + gj;
                uint32_t a = 40960 + s*4096 + gc*128 + (((px >> 3) ^ (gc & 7))*16) + (px & 7)*2;
                *(__half*)(sm + a) = hvals[nw];
            }
        }
        if (u + 1 < u1) prefetch(u + 1);
        __syncthreads();

        float acc[4][4][4];
#pragma unroll
        for (int i = 0; i < 4; i++)
#pragma unroll
            for (int j = 0; j < 4; j++)
#pragma unroll
                for (int rr = 0; rr < 4; rr++) acc[i][j][rr] = 0.0f;

#pragma unroll
        for (int kk = 0; kk < 2; kk++) {
            uint32_t ah[4][4], am[4][4];
#pragma unroll
            for (int mt = 0; mt < 4; mt++) {
                int row = wm*64 + mt*16 + (lane & 15);
                uint32_t addr = su + row*80 + (kk*2 + (lane >> 4))*16;
                ldsm4(ah[mt], addr);
                ldsm4(am[mt], addr + 20480);
            }
            const int krow = kk*16 + (lane & 15);
            uint32_t bh[2][4];
#pragma unroll
            for (int tt = 0; tt < 2; tt++) {
                int cc = wn*4 + tt*2 + (lane >> 4);
                uint32_t addr = su + 40960 + s*4096 + krow*128 + ((cc ^ (krow & 7))*16);
                ldsm4t(bh[tt], addr);
            }
#pragma unroll
            for (int mt = 0; mt < 4; mt++) {
#pragma unroll
                for (int nt = 0; nt < 4; nt++) {
                    int tt = nt >> 1, hf = nt & 1;
                    mma_f16(acc[mt][nt], ah[mt], bh[tt][hf*2], bh[tt][hf*2+1]);
                    mma_f16(acc[mt][nt], am[mt], bh[tt][hf*2], bh[tt][hf*2+1]);
                }
            }
        }

        const int h = hp*2 + wn;
#pragma unroll
        for (int mt = 0; mt < 4; mt++) {
            int ch0 = wm*64 + mt*16 + rq;
#pragma unroll
            for (int nt = 0; nt < 4; nt++) {
                int w = wblk*32 + nt*8 + cq;
                float* p0 = out + ((size_t)(b*CHN + ch0))*HW + (size_t)h*160 + w;
                *(float2*)p0          = make_float2(acc[mt][nt][0] + bb[mt][0], acc[mt][nt][1] + bb[mt][0]);
                *(float2*)(p0 + 8*HW) = make_float2(acc[mt][nt][2] + bb[mt][1], acc[mt][nt][3] + bb[mt][1]);
            }
        }
    }
}

// ---------------------------------------------------------------------------
extern "C" void kernel_launch(void* const* d_in, const int* in_sizes, int n_in,
                              void* d_out, int out_size)
{
    (void)in_sizes; (void)n_in; (void)out_size;
    const float* rgb   = (const float*)d_in[0];
    const float* depth = (const float*)d_in[1];
    const float* Wq    = (const float*)d_in[2];
    const float* bq    = (const float*)d_in[3];
    const float* Wk    = (const float*)d_in[4];
    const float* bk    = (const float*)d_in[5];
    const float* Wv    = (const float*)d_in[6];
    const float* bv    = (const float*)d_in[7];
    const float* Wu    = (const float*)d_in[8];
    const float* bu    = (const float*)d_in[9];
    float* out = (float*)d_out;

    cudaFuncSetAttribute(k_projT,   cudaFuncAttributeMaxDynamicSharedMemorySize, 114688);
    cudaFuncSetAttribute(k_gemm<0>, cudaFuncAttributeMaxDynamicSharedMemorySize, 73728);
    cudaFuncSetAttribute(k_gemm<1>, cudaFuncAttributeMaxDynamicSharedMemorySize, 73728);
    cudaFuncSetAttribute(k_final,   cudaFuncAttributeMaxDynamicSharedMemorySize, 49152);

    k_wsplit <<<96, 256>>>(Wq, Wv, Wk, Wu);
    k_projT  <<<148, 384, 114688>>>(rgb, depth, bq, bk, bv);
    k_gemm<0><<<dim3(8, 4, NB), 256, 73728>>>();
    k_softmax<<<NB*DD, 128>>>();
    k_gemm<1><<<dim3(25, 4, NB), 256, 73728>>>();
    k_final  <<<296, 256, 49152>>>(bu, out);
}

// round 15
// speedup vs baseline: 1.3890x; 1.3890x over previous
#include <cuda_runtime.h>
#include <cuda_fp16.h>
#include <cstdint>

#define NB  8
#define CHN 256
#define HW  25600
#define DD  512
#define NN  1600
#define NNP 1664

// ---------------- scratch (__device__ globals; allocation-free) ------------
__device__ float g_sc[NB*DD*DD];    // scores fp32 [d][e']
__device__ __align__(128) __half g_oph[NB*DD*NN];     // attn@V output fp16 [d][n]
__device__ __align__(128) __half g_fq_hi[NB*DD*NN];   // [d][n] single plane
__device__ __align__(128) __half g_fk_hi[NB*DD*NN];   // [e'][n] single plane
__device__ __align__(128) __half g_fvT_hi[NB*NNP*DD]; // [n][e'] single plane
__device__ __align__(128) __half g_at_hi[NB*DD*DD];   // [d][e'] single plane
__device__ __align__(128) __half g_w_hi[96*256];      // qkv weights single plane
__device__ __align__(128) __half g_wu_hi[256*32];     // Wu fp16 hi/mi planes
__device__ __align__(128) __half g_wu_mi[256*32];

typedef unsigned long long u64;

// ---------------- PTX helpers (baseline ISA only) ---------------------------
__device__ __forceinline__ uint32_t smem_u32(const void* p) {
    uint32_t a;
    asm("{ .reg .u64 t; cvta.to.shared.u64 t, %1; cvt.u32.u64 %0, t; }" : "=r"(a) : "l"(p));
    return a;
}
__device__ __forceinline__ void cpa16(uint32_t s, const void* g) {
    asm volatile("cp.async.cg.shared.global [%0], [%1], 16;" :: "r"(s), "l"(g));
}
#define CPA_COMMIT() asm volatile("cp.async.commit_group;" ::: "memory")

__device__ __forceinline__ void ldsm4(uint32_t* r, uint32_t a) {
    asm volatile("ldmatrix.sync.aligned.m8n8.x4.shared.b16 {%0,%1,%2,%3}, [%4];"
        : "=r"(r[0]), "=r"(r[1]), "=r"(r[2]), "=r"(r[3]) : "r"(a));
}
__device__ __forceinline__ void ldsm4t(uint32_t* r, uint32_t a) {
    asm volatile("ldmatrix.sync.aligned.m8n8.x4.trans.shared.b16 {%0,%1,%2,%3}, [%4];"
        : "=r"(r[0]), "=r"(r[1]), "=r"(r[2]), "=r"(r[3]) : "r"(a));
}
__device__ __forceinline__ void ldsm2t(uint32_t* r, uint32_t a) {
    asm volatile("ldmatrix.sync.aligned.m8n8.x2.trans.shared.b16 {%0,%1}, [%2];"
        : "=r"(r[0]), "=r"(r[1]) : "r"(a));
}
__device__ __forceinline__ void mma_f16(float* d, const uint32_t* a, uint32_t b0, uint32_t b1) {
    asm volatile(
        "mma.sync.aligned.m16n8k16.row.col.f32.f16.f16.f32 "
        "{%0,%1,%2,%3},{%4,%5,%6,%7},{%8,%9},{%0,%1,%2,%3};"
        : "+f"(d[0]), "+f"(d[1]), "+f"(d[2]), "+f"(d[3])
        : "r"(a[0]), "r"(a[1]), "r"(a[2]), "r"(a[3]), "r"(b0), "r"(b1));
}

// pack 2 floats -> fp16x2 (lo=a, hi=b)
__device__ __forceinline__ uint32_t pack_h2(float a, float b) {
    uint32_t r;
    asm("cvt.rn.f16x2.f32 %0, %1, %2;" : "=r"(r) : "f"(b), "f"(a));
    return r;
}

// ---------------------------------------------------------------------------
// K-1: W q/v/k rows -> single fp16 plane; Wu -> fp16 hi/mi planes.
// ---------------------------------------------------------------------------
__global__ __launch_bounds__(256) void k_wsplit(
    const float* __restrict__ Wq, const float* __restrict__ Wv, const float* __restrict__ Wk,
    const float* __restrict__ Wu)
{
    int i = blockIdx.x * 256 + threadIdx.x;
    if (i < 96*256) {
        int r = i >> 8, kk = i & 255;
        float v = (r < 32) ? Wq[r*256 + kk] : ((r < 64) ? Wv[(r-32)*256 + kk] : Wk[(r-64)*256 + kk]);
        g_w_hi[i] = __float2half_rn(v);
    }
    if (i < 256*32) {
        float v = Wu[i];
        __half h = __float2half_rn(v);
        g_wu_hi[i] = h;
        g_wu_mi[i] = __float2half_rn(v - __half2float(h));
    }
}

// ---------------------------------------------------------------------------
// K1: PERSISTENT tensor-core fused q/k/v 1x1 conv + pixel_unshuffle.
// 384 threads / 12 warps (3/SMSP), warp grid 3m x 4n, warp tile 32x40.
// Single-pass fp16: W (1 plane, smem-resident) x x (1 fp16 plane per source).
// ---------------------------------------------------------------------------
__global__ __launch_bounds__(384, 1) void k_projT(
    const float* __restrict__ rgb, const float* __restrict__ depth,
    const float* __restrict__ bq, const float* __restrict__ bk,
    const float* __restrict__ bv)
{
    extern __shared__ __align__(1024) char sm[];
    const int t = threadIdx.x, lane = t & 31, wid = t >> 5;
    const int wn = wid & 3, wm = wid >> 2;       // wm 0..2, wn 0..3
    const uint32_t su = smem_u32(sm);
    const uint32_t XB = su + 49152;
    float* const epi = (float*)(sm + 49152);

    // ---- W plane into smem (once per CTA) ----
    for (int i = t; i < 96*32; i += 384) {
        int m = i >> 5, c = i & 31;
        uint4 v1 = *(const uint4*)((const char*)g_w_hi + m*512 + c*16);
        int sw = (c ^ (m & 7)) * 16;
        *(uint4*)(sm + m*512 + sw) = v1;
    }

    float bias_v[2][2];
#pragma unroll
    for (int mt = 0; mt < 2; mt++)
#pragma unroll
        for (int hh = 0; hh < 2; hh++) {
            int r = wm*32 + mt*16 + (lane >> 2) + hh*8;
            bias_v[mt][hh] = (r < 32) ? bq[r] : ((r < 64) ? bv[r-32] : bk[r-64]);
        }

    // per-thread ldg mapping: 2560 float4 items (src x 32 cin x 40 c4)
    int cin_[7], c4_[7], pl_[7];
    bool val_[7];
#pragma unroll
    for (int j = 0; j < 7; j++) {
        int item = t + j*384;
        val_[j] = item < 2560;
        int it2 = val_[j] ? item : 0;
        int src = (it2 >= 1280) ? 1 : 0;
        int rem = it2 - src*1280;
        cin_[j] = rem / 40; c4_[j] = rem % 40;
        pl_[j]  = src ? 12288 : 0;
    }
    __syncthreads();

    const int cta = blockIdx.x;
    int u        = (1280 * cta) / 148;
    const int u1 = (1280 * (cta + 1)) / 148;

    int b = u / 160, h = u - b*160;
    const float* db = depth + (size_t)b*CHN*HW;
    const float* rb = rgb   + (size_t)b*CHN*HW;
    size_t rowoff = (size_t)h * 160;

    float4 rv[7];
    auto ldg_chunk = [&](int c, const float* dB, const float* rB, size_t ro) {
#pragma unroll
        for (int j = 0; j < 7; j++) {
            if (val_[j]) {
                const float* bp = pl_[j] ? rB : dB;
                rv[j] = *(const float4*)(bp + (size_t)(c*32 + cin_[j])*HW + ro + c4_[j]*4);
            }
        }
    };
    auto sts_chunk = [&](int s) {
        const int soff = 49152 + s*24576;
#pragma unroll
        for (int j = 0; j < 7; j++) {
            if (val_[j]) {
                int row = cin_[j], c4 = c4_[j];
                int a = soff + pl_[j] + row*384 + (((c4 >> 1) ^ (row & 7)) * 16) + (c4 & 1)*8;
                uint32_t h01 = pack_h2(rv[j].x, rv[j].y);
                uint32_t h23 = pack_h2(rv[j].z, rv[j].w);
                *(uint2*)(sm + a) = make_uint2(h01, h23);
            }
        }
    };

    ldg_chunk(0, db, rb, rowoff);

    for (; u < u1; u++) {
        const int ip = h & 3, hn = h >> 2, curb = b;

        int nb = b, nh = h + 1;
        if (nh == 160) { nh = 0; nb = b + 1; }
        const bool has_next = (u + 1 < u1);
        const float* ndb = depth + (size_t)nb*CHN*HW;
        const float* nrb = rgb   + (size_t)nb*CHN*HW;
        const size_t nro = (size_t)nh * 160;

        sts_chunk(0);
        ldg_chunk(1, db, rb, rowoff);

        float acc[2][5][4];
#pragma unroll
        for (int i = 0; i < 2; i++)
#pragma unroll
            for (int j = 0; j < 5; j++)
#pragma unroll
                for (int r = 0; r < 4; r++) acc[i][j][r] = 0.0f;

        const int pls = (wm == 2) ? 12288 : 0;   // this warp's source plane

        for (int c = 0; c < 8; c++) {
            __syncthreads();
            if (c + 1 < 8) sts_chunk((c + 1) & 1);
            if (c + 2 < 8)                    ldg_chunk(c + 2, db, rb, rowoff);
            else if (c == 6 && has_next)      ldg_chunk(0, ndb, nrb, nro);
            __syncthreads();

            const uint32_t xs = XB + (c & 1)*24576;
#pragma unroll
            for (int kk = 0; kk < 2; kk++) {
                uint32_t ah[2][4];
#pragma unroll
                for (int mt = 0; mt < 2; mt++) {
                    int m = wm*32 + mt*16 + (lane & 15);
                    int ca = c*4 + kk*2 + (lane >> 4);
                    uint32_t addr = su + m*512 + (ca ^ (m & 7))*16;
                    ldsm4(ah[mt], addr);
                }
                const int krow = kk*16 + (lane & 15);
                const int swz = krow & 7;
                const uint32_t rbase_a = xs + pls + krow*384;
                uint32_t bh[2][4], bh2[2];
#pragma unroll
                for (int tt = 0; tt < 2; tt++) {
                    int cc = wn*5 + tt*2 + (lane >> 4);
                    ldsm4t(bh[tt], rbase_a + (cc ^ swz)*16);
                }
                {
                    int cc = wn*5 + 4;
                    ldsm2t(bh2, rbase_a + (cc ^ swz)*16);
                }
#pragma unroll
                for (int mt = 0; mt < 2; mt++) {
#pragma unroll
                    for (int nt = 0; nt < 5; nt++) {
                        uint32_t b0, b1;
                        if (nt < 4) {
                            int g = nt >> 1, hf = nt & 1;
                            b0 = bh[g][hf*2]; b1 = bh[g][hf*2+1];
                        } else {
                            b0 = bh2[0]; b1 = bh2[1];
                        }
                        mma_f16(acc[mt][nt], ah[mt], b0, b1);
                    }
                }
            }
        }

        // ---- epilogue: stage into epi, coalesced drain ----
        __syncthreads();
#pragma unroll
        for (int mt = 0; mt < 2; mt++) {
#pragma unroll
            for (int nt = 0; nt < 5; nt++) {
                int col0 = wn*40 + nt*8 + (lane & 3)*2;
                int nw = col0 >> 2, j0 = col0 & 3;
#pragma unroll
                for (int hh = 0; hh < 2; hh++) {
                    int r = wm*32 + mt*16 + (lane >> 2) + hh*8;
                    epi[(j0*96 + r)*42 + nw]     = acc[mt][nt][hh*2]   + bias_v[mt][hh];
                    epi[((j0+1)*96 + r)*42 + nw] = acc[mt][nt][hh*2+1] + bias_v[mt][hh];
                }
            }
        }
        __syncthreads();

        for (int tk = wid; tk < 416; tk += 12) {
            if (tk < 256) {
                if (lane < 20) {
                    int rr = tk >> 2, j = tk & 3;
                    int row = (rr < 32) ? rr : rr + 32;
                    float2 v = *(const float2*)&epi[(j*96 + row)*42 + lane*2];
                    uint32_t hi = pack_h2(v.x, v.y);
                    int dd = (rr < 32) ? (rr*16 + ip*4 + j)
                                       : ((ip*4 + j)*32 + (rr - 32));
                    size_t base = ((size_t)(curb*DD + dd))*NN + hn*40 + lane*2;
                    __half* dh = (rr < 32) ? g_fq_hi : g_fk_hi;
                    *(uint32_t*)(dh + base) = hi;
                }
            } else {
                if (lane < 16) {
                    int tv = tk - 256;
                    int nw = tv >> 2, j = tv & 3;
                    float v0 = epi[(j*96 + 32 + lane*2)*42 + nw];
                    float v1 = epi[(j*96 + 33 + lane*2)*42 + nw];
                    uint32_t hi = pack_h2(v0, v1);
                    int n = hn*40 + nw;
                    size_t base = ((size_t)curb*NNP + n)*DD + (ip*4 + j)*32 + lane*2;
                    *(uint32_t*)(g_fvT_hi + base) = hi;
                }
            }
        }
        __syncthreads();   // epi region reused as x stages next unit

        b = nb; h = nh; db = ndb; rb = nrb; rowoff = nro;
    }
}

// ---------------------------------------------------------------------------
// Generic 128x64-tile mma.sync single-pass fp16 GEMM (2 CTAs/SM, 3 stages):
// MODE 0: scores (A=fq_hi, B=fk_hi, K=1600, C=g_sc fp32 [512x512])
// MODE 1: attn@V (A=at_hi, B=fvT_hi, K=512, C=g_oph fp16 [512x1600])
// stage: Ahi 16K | Bhi 8K ; stride 24576; 3 stages = 72KB.
// (exact round-11 champion configuration)
// ---------------------------------------------------------------------------
template<int MODE>
__global__ __launch_bounds__(256, 2) void k_gemm()
{
    constexpr int K    = (MODE == 0) ? 1600 : 512;
    constexpr int LD   = (MODE == 0) ? 1600 : 512;
    constexpr int LDC  = (MODE == 0) ? 512  : 1600;
    constexpr long SA  = (MODE == 0) ? (long)DD*NN : (long)DD*DD;
    constexpr long SB  = (MODE == 0) ? (long)DD*NN : (long)NNP*DD;
    constexpr int NCH  = K / 64;

    extern __shared__ __align__(1024) char dsm[];

    const int b  = blockIdx.z;
    const int m0 = blockIdx.y * 128;
    const int n0 = blockIdx.x * 64;
    const int t    = threadIdx.x;
    const int lane = t & 31;
    const int wid  = t >> 5;
    const int wm   = wid & 3;
    const int wn   = wid >> 2;

    const uint32_t smem_u = smem_u32(dsm);

    const __half* Ahi = (MODE == 0 ? g_fq_hi : g_at_hi)  + b*SA + (long)m0*LD;
    const __half* Bhi = (MODE == 0 ? g_fk_hi : g_fvT_hi) + b*SB + (long)n0*LD;

    auto load_stage = [&](int s, int kc) {
        uint32_t base = smem_u + s*24576;
#pragma unroll
        for (int ii = 0; ii < 4; ii++) {
            int i = t + ii*256;
            int row = i >> 3, seg = i & 7;
            uint32_t off = row*128 + seg*16;
            uint32_t sw  = off ^ ((off >> 3) & 0x70);
            long go = (long)row*LD + kc;
            cpa16(base + sw, (const char*)(Ahi + go) + seg*16);
        }
#pragma unroll
        for (int ii = 0; ii < 2; ii++) {
            int i = t + ii*256;
            int row = i >> 3, seg = i & 7;
            uint32_t off = row*128 + seg*16;
            uint32_t sw  = off ^ ((off >> 3) & 0x70);
            long go = (long)row*LD + kc;
            cpa16(base + 16384 + sw, (const char*)(Bhi + go) + seg*16);
        }
        CPA_COMMIT();
    };

    float acc[2][4][4];
#pragma unroll
    for (int i = 0; i < 2; i++)
#pragma unroll
        for (int j = 0; j < 4; j++)
#pragma unroll
            for (int r = 0; r < 4; r++) acc[i][j][r] = 0.0f;

    load_stage(0, 0);
    load_stage(1, 64);
    load_stage(2, 128);   // NCH >= 8 in both modes

    const int lr = lane & 15;
    const int lc = lane >> 4;

    for (int c = 0; c < NCH; c++) {
        const int s = c - (c/3)*3;
        if (c + 2 < NCH)      asm volatile("cp.async.wait_group 2;" ::: "memory");
        else if (c + 1 < NCH) asm volatile("cp.async.wait_group 1;" ::: "memory");
        else                  asm volatile("cp.async.wait_group 0;" ::: "memory");
        __syncthreads();

        const uint32_t base = smem_u + s*24576;
#pragma unroll
        for (int kk = 0; kk < 4; kk++) {
            uint32_t a_hi[2][4];
#pragma unroll
            for (int mt = 0; mt < 2; mt++) {
                int row = wm*32 + mt*16 + lr;
                uint32_t off = row*128 + kk*32 + lc*16;
                uint32_t sw  = off ^ ((off >> 3) & 0x70);
                ldsm4(a_hi[mt], base + sw);
            }
            uint32_t b_hi[2][4];
#pragma unroll
            for (int bt = 0; bt < 2; bt++) {
                int row = wn*32 + bt*16 + lr;
                uint32_t off = row*128 + kk*32 + lc*16;
                uint32_t sw  = off ^ ((off >> 3) & 0x70);
                ldsm4(b_hi[bt], base + 16384 + sw);
            }
#pragma unroll
            for (int mt = 0; mt < 2; mt++) {
#pragma unroll
                for (int nt = 0; nt < 4; nt++) {
                    int bt = nt >> 1, hf = nt & 1;
                    mma_f16(acc[mt][nt], a_hi[mt], b_hi[bt][hf], b_hi[bt][hf+2]);
                }
            }
        }
        __syncthreads();
        if (c + 3 < NCH) load_stage(s, (c + 3)*64);
    }

    const int rq = lane >> 2;
    const int cq = (lane & 3) * 2;
#pragma unroll
    for (int mt = 0; mt < 2; mt++) {
#pragma unroll
        for (int nt = 0; nt < 4; nt++) {
            int col = n0 + wn*32 + nt*8 + cq;
            int row = m0 + wm*32 + mt*16 + rq;
            if (MODE == 0) {
                float* p0 = g_sc + (long)b*DD*DD + (long)row*LDC + col;
                *(float2*)p0            = make_float2(acc[mt][nt][0], acc[mt][nt][1]);
                *(float2*)(p0 + 8L*LDC) = make_float2(acc[mt][nt][2], acc[mt][nt][3]);
            } else {
                __half* p0 = g_oph + (long)b*DD*NN + (long)row*LDC + col;
                *(uint32_t*)p0            = pack_h2(acc[mt][nt][0], acc[mt][nt][1]);
                *(uint32_t*)(p0 + 8L*LDC) = pack_h2(acc[mt][nt][2], acc[mt][nt][3]);
            }
        }
    }
}

// ---------------------------------------------------------------------------
// K3: softmax over rows of g_sc, writes attn as single fp16 plane.
// ---------------------------------------------------------------------------
__global__ __launch_bounds__(128) void k_softmax()
{
    __shared__ float red[8];
    const size_t row = blockIdx.x;
    const float* s = g_sc + row * DD;
    const int t = threadIdx.x;

    float v0 = s[t], v1 = s[t+128], v2 = s[t+256], v3 = s[t+384];
    float m = fmaxf(fmaxf(v0, v1), fmaxf(v2, v3));
#pragma unroll
    for (int o = 16; o; o >>= 1) m = fmaxf(m, __shfl_xor_sync(0xffffffffu, m, o));
    if ((t & 31) == 0) red[t >> 5] = m;
    __syncthreads();
    m = fmaxf(fmaxf(red[0], red[1]), fmaxf(red[2], red[3]));

    const float inv = 0.04419417382415922f;  // 1/sqrt(512)
    float e0 = __expf((v0 - m) * inv);
    float e1 = __expf((v1 - m) * inv);
    float e2 = __expf((v2 - m) * inv);
    float e3 = __expf((v3 - m) * inv);
    float sum = e0 + e1 + e2 + e3;
#pragma unroll
    for (int o = 16; o; o >>= 1) sum += __shfl_xor_sync(0xffffffffu, sum, o);
    if ((t & 31) == 0) red[4 + (t >> 5)] = sum;
    __syncthreads();
    float r = 1.0f / (red[4] + red[5] + red[6] + red[7]);

    size_t base = row * DD;
    g_at_hi[base + t]       = __float2half_rn(e0 * r);
    g_at_hi[base + t + 128] = __float2half_rn(e1 * r);
    g_at_hi[base + t + 256] = __float2half_rn(e2 * r);
    g_at_hi[base + t + 384] = __float2half_rn(e3 * r);
}

// ---------------------------------------------------------------------------
// K5: PERSISTENT pixel_shuffle gather + final 1x1 conv (32 -> 256).
// fp16 2-pass: Wu (hi/mi planes from wsplit) x op (1 fp16 plane).
// ---------------------------------------------------------------------------
__global__ __launch_bounds__(256, 2) void k_final(
    const float* __restrict__ bu, float* __restrict__ out)
{
    extern __shared__ __align__(1024) char sm[];
    const uint32_t su = smem_u32(sm);
    const int t = threadIdx.x, lane = t & 31, wid = t >> 5;
    const int wm = wid & 3, wn = wid >> 2;
    const int rq = lane >> 2, cq = (lane & 3) * 2;

    // ---- load Wu planes once: row t at 80B pitch ----
    {
        const uint4* src_h = (const uint4*)((const char*)g_wu_hi + t*64);
        const uint4* src_m = (const uint4*)((const char*)g_wu_mi + t*64);
#pragma unroll
        for (int c = 0; c < 4; c++) {
            *(uint4*)(sm + t*80 + c*16)         = src_h[c];
            *(uint4*)(sm + 20480 + t*80 + c*16) = src_m[c];
        }
    }

    float bb[4][2];
#pragma unroll
    for (int mt = 0; mt < 4; mt++) {
        int ch0 = wm*64 + mt*16 + rq;
        bb[mt][0] = bu[ch0];
        bb[mt][1] = bu[ch0 + 8];
    }

    const int gc = t >> 3;
    const int ii = (t >> 2) & 1;
    const int gj = t & 3;

    const int cta = blockIdx.x;
    int u        = (3200 * cta) / 296;
    const int u1 = (3200 * (cta + 1)) / 296;

    uint4 hv;   // 8 fp16 values
    auto prefetch = [&](int uu) {
        int pb = uu / 400, r = uu - pb*400;
        int php = r / 5, pwb = r - (r/5)*5;
        int i0 = (2*php) & 3, hn = php >> 1;
        int d  = gc*16 + (i0 + ii)*4 + gj;
        hv = *(const uint4*)(g_oph + ((size_t)(pb*DD + d))*NN + hn*40 + pwb*8);
    };
    if (u < u1) prefetch(u);

    for (; u < u1; u++) {
        const int s = u & 1;
        const int b = u / 400, r = u - b*400;
        const int hp = r / 5, wblk = r - (r/5)*5;

        __syncthreads();   // stage s free; Wu visible on first iter

        // ---- stage B (already fp16; scatter into swizzled [32 c][64 px]) ----
        {
            const __half* hvals = (const __half*)&hv;
#pragma unroll
            for (int nw = 0; nw < 8; nw++) {
                int px = ii*32 + nw*4 + gj;
                uint32_t a = 40960 + s*4096 + gc*128 + (((px >> 3) ^ (gc & 7))*16) + (px & 7)*2;
                *(__half*)(sm + a) = hvals[nw];
            }
        }
        if (u + 1 < u1) prefetch(u + 1);   // overlap next gather with MMA
        __syncthreads();

        // ---- MMA (stage s): 2 passes (Wu_hi + Wu_mi) x op ----
        float acc[4][4][4];
#pragma unroll
        for (int i = 0; i < 4; i++)
#pragma unroll
            for (int j = 0; j < 4; j++)
#pragma unroll
                for (int rr = 0; rr < 4; rr++) acc[i][j][rr] = 0.0f;

#pragma unroll
        for (int kk = 0; kk < 2; kk++) {
            uint32_t ah[4][4], am[4][4];
#pragma unroll
            for (int mt = 0; mt < 4; mt++) {
                int row = wm*64 + mt*16 + (lane & 15);
                uint32_t addr = su + row*80 + (kk*2 + (lane >> 4))*16;
                ldsm4(ah[mt], addr);
                ldsm4(am[mt], addr + 20480);
            }
            const int krow = kk*16 + (lane & 15);
            uint32_t bh[2][4];
#pragma unroll
            for (int tt = 0; tt < 2; tt++) {
                int cc = wn*4 + tt*2 + (lane >> 4);
                uint32_t addr = su + 40960 + s*4096 + krow*128 + ((cc ^ (krow & 7))*16);
                ldsm4t(bh[tt], addr);
            }
#pragma unroll
            for (int mt = 0; mt < 4; mt++) {
#pragma unroll
                for (int nt = 0; nt < 4; nt++) {
                    int tt = nt >> 1, hf = nt & 1;
                    mma_f16(acc[mt][nt], ah[mt], bh[tt][hf*2], bh[tt][hf*2+1]);
                    mma_f16(acc[mt][nt], am[mt], bh[tt][hf*2], bh[tt][hf*2+1]);
                }
            }
        }

        // ---- epilogue: bias + float2 stores ----
        const int h = hp*2 + wn;
#pragma unroll
        for (int mt = 0; mt < 4; mt++) {
            int ch0 = wm*64 + mt*16 + rq;
#pragma unroll
            for (int nt = 0; nt < 4; nt++) {
                int w = wblk*32 + nt*8 + cq;
                float* p0 = out + ((size_t)(b*CHN + ch0))*HW + (size_t)h*160 + w;
                *(float2*)p0          = make_float2(acc[mt][nt][0] + bb[mt][0], acc[mt][nt][1] + bb[mt][0]);
                *(float2*)(p0 + 8*HW) = make_float2(acc[mt][nt][2] + bb[mt][1], acc[mt][nt][3] + bb[mt][1]);
            }
        }
    }
}

// ---------------------------------------------------------------------------
extern "C" void kernel_launch(void* const* d_in, const int* in_sizes, int n_in,
                              void* d_out, int out_size)
{
    (void)in_sizes; (void)n_in; (void)out_size;
    const float* rgb   = (const float*)d_in[0];
    const float* depth = (const float*)d_in[1];
    const float* Wq    = (const float*)d_in[2];
    const float* bq    = (const float*)d_in[3];
    const float* Wk    = (const float*)d_in[4];
    const float* bk    = (const float*)d_in[5];
    const float* Wv    = (const float*)d_in[6];
    const float* bv    = (const float*)d_in[7];
    const float* Wu    = (const float*)d_in[8];
    const float* bu    = (const float*)d_in[9];
    float* out = (float*)d_out;

    cudaFuncSetAttribute(k_projT,   cudaFuncAttributeMaxDynamicSharedMemorySize, 114688);
    cudaFuncSetAttribute(k_gemm<0>, cudaFuncAttributeMaxDynamicSharedMemorySize, 73728);
    cudaFuncSetAttribute(k_gemm<1>, cudaFuncAttributeMaxDynamicSharedMemorySize, 73728);
    cudaFuncSetAttribute(k_final,   cudaFuncAttributeMaxDynamicSharedMemorySize, 49152);

    k_wsplit <<<96, 256>>>(Wq, Wv, Wk, Wu);
    k_projT  <<<148, 384, 114688>>>(rgb, depth, bq, bk, bv);
    k_gemm<0><<<dim3(8, 4, NB), 256, 73728>>>();
    k_softmax<<<NB*DD, 128>>>();
    k_gemm<1><<<dim3(25, 4, NB), 256, 73728>>>();
    k_final  <<<296, 256, 49152>>>(bu, out);
}

// round 16
// speedup vs baseline: 1.3998x; 1.0078x over previous
#include <cuda_runtime.h>
#include <cuda_fp16.h>
#include <cstdint>

#define NB  8
#define CHN 256
#define HW  25600
#define DD  512
#define NN  1600
#define NNP 1664

// ---------------- scratch (__device__ globals; allocation-free) ------------
__device__ float g_sc[NB*DD*DD];    // scores fp32 [d][e']
__device__ __align__(128) __half g_oph[NB*DD*NN];     // attn@V output fp16 [d][n]
__device__ __align__(128) __half g_fq_hi[NB*DD*NN];   // [d][n] single plane
__device__ __align__(128) __half g_fk_hi[NB*DD*NN];   // [e'][n] single plane
__device__ __align__(128) __half g_fvT_hi[NB*NNP*DD]; // [n][e'] single plane
__device__ __align__(128) __half g_at_hi[NB*DD*DD];   // [d][e'] single plane
__device__ __align__(128) __half g_w_hi[96*256];      // qkv weights single plane
__device__ __align__(128) __half g_wu_hi[256*32];     // Wu single fp16 plane

typedef unsigned long long u64;

// ---------------- PTX helpers (baseline ISA only) ---------------------------
__device__ __forceinline__ uint32_t smem_u32(const void* p) {
    uint32_t a;
    asm("{ .reg .u64 t; cvta.to.shared.u64 t, %1; cvt.u32.u64 %0, t; }" : "=r"(a) : "l"(p));
    return a;
}
__device__ __forceinline__ void cpa16(uint32_t s, const void* g) {
    asm volatile("cp.async.cg.shared.global [%0], [%1], 16;" :: "r"(s), "l"(g));
}
#define CPA_COMMIT() asm volatile("cp.async.commit_group;" ::: "memory")

__device__ __forceinline__ void ldsm4(uint32_t* r, uint32_t a) {
    asm volatile("ldmatrix.sync.aligned.m8n8.x4.shared.b16 {%0,%1,%2,%3}, [%4];"
        : "=r"(r[0]), "=r"(r[1]), "=r"(r[2]), "=r"(r[3]) : "r"(a));
}
__device__ __forceinline__ void ldsm4t(uint32_t* r, uint32_t a) {
    asm volatile("ldmatrix.sync.aligned.m8n8.x4.trans.shared.b16 {%0,%1,%2,%3}, [%4];"
        : "=r"(r[0]), "=r"(r[1]), "=r"(r[2]), "=r"(r[3]) : "r"(a));
}
__device__ __forceinline__ void ldsm2t(uint32_t* r, uint32_t a) {
    asm volatile("ldmatrix.sync.aligned.m8n8.x2.trans.shared.b16 {%0,%1}, [%2];"
        : "=r"(r[0]), "=r"(r[1]) : "r"(a));
}
__device__ __forceinline__ void mma_f16(float* d, const uint32_t* a, uint32_t b0, uint32_t b1) {
    asm volatile(
        "mma.sync.aligned.m16n8k16.row.col.f32.f16.f16.f32 "
        "{%0,%1,%2,%3},{%4,%5,%6,%7},{%8,%9},{%0,%1,%2,%3};"
        : "+f"(d[0]), "+f"(d[1]), "+f"(d[2]), "+f"(d[3])
        : "r"(a[0]), "r"(a[1]), "r"(a[2]), "r"(a[3]), "r"(b0), "r"(b1));
}

// pack 2 floats -> fp16x2 (lo=a, hi=b)
__device__ __forceinline__ uint32_t pack_h2(float a, float b) {
    uint32_t r;
    asm("cvt.rn.f16x2.f32 %0, %1, %2;" : "=r"(r) : "f"(b), "f"(a));
    return r;
}

// ---------------------------------------------------------------------------
// K-1: W q/v/k rows -> single fp16 plane; Wu -> single fp16 plane.
// ---------------------------------------------------------------------------
__global__ __launch_bounds__(256) void k_wsplit(
    const float* __restrict__ Wq, const float* __restrict__ Wv, const float* __restrict__ Wk,
    const float* __restrict__ Wu)
{
    int i = blockIdx.x * 256 + threadIdx.x;
    if (i < 96*256) {
        int r = i >> 8, kk = i & 255;
        float v = (r < 32) ? Wq[r*256 + kk] : ((r < 64) ? Wv[(r-32)*256 + kk] : Wk[(r-64)*256 + kk]);
        g_w_hi[i] = __float2half_rn(v);
    }
    if (i < 256*32) {
        g_wu_hi[i] = __float2half_rn(Wu[i]);
    }
}

// ---------------------------------------------------------------------------
// K1: PERSISTENT tensor-core fused q/k/v 1x1 conv + pixel_unshuffle.
// (exact champion version)
// ---------------------------------------------------------------------------
__global__ __launch_bounds__(384, 1) void k_projT(
    const float* __restrict__ rgb, const float* __restrict__ depth,
    const float* __restrict__ bq, const float* __restrict__ bk,
    const float* __restrict__ bv)
{
    extern __shared__ __align__(1024) char sm[];
    const int t = threadIdx.x, lane = t & 31, wid = t >> 5;
    const int wn = wid & 3, wm = wid >> 2;       // wm 0..2, wn 0..3
    const uint32_t su = smem_u32(sm);
    const uint32_t XB = su + 49152;
    float* const epi = (float*)(sm + 49152);

    // ---- W plane into smem (once per CTA) ----
    for (int i = t; i < 96*32; i += 384) {
        int m = i >> 5, c = i & 31;
        uint4 v1 = *(const uint4*)((const char*)g_w_hi + m*512 + c*16);
        int sw = (c ^ (m & 7)) * 16;
        *(uint4*)(sm + m*512 + sw) = v1;
    }

    float bias_v[2][2];
#pragma unroll
    for (int mt = 0; mt < 2; mt++)
#pragma unroll
        for (int hh = 0; hh < 2; hh++) {
            int r = wm*32 + mt*16 + (lane >> 2) + hh*8;
            bias_v[mt][hh] = (r < 32) ? bq[r] : ((r < 64) ? bv[r-32] : bk[r-64]);
        }

    // per-thread ldg mapping: 2560 float4 items (src x 32 cin x 40 c4)
    int cin_[7], c4_[7], pl_[7];
    bool val_[7];
#pragma unroll
    for (int j = 0; j < 7; j++) {
        int item = t + j*384;
        val_[j] = item < 2560;
        int it2 = val_[j] ? item : 0;
        int src = (it2 >= 1280) ? 1 : 0;
        int rem = it2 - src*1280;
        cin_[j] = rem / 40; c4_[j] = rem % 40;
        pl_[j]  = src ? 12288 : 0;
    }
    __syncthreads();

    const int cta = blockIdx.x;
    int u        = (1280 * cta) / 148;
    const int u1 = (1280 * (cta + 1)) / 148;

    int b = u / 160, h = u - b*160;
    const float* db = depth + (size_t)b*CHN*HW;
    const float* rb = rgb   + (size_t)b*CHN*HW;
    size_t rowoff = (size_t)h * 160;

    float4 rv[7];
    auto ldg_chunk = [&](int c, const float* dB, const float* rB, size_t ro) {
#pragma unroll
        for (int j = 0; j < 7; j++) {
            if (val_[j]) {
                const float* bp = pl_[j] ? rB : dB;
                rv[j] = *(const float4*)(bp + (size_t)(c*32 + cin_[j])*HW + ro + c4_[j]*4);
            }
        }
    };
    auto sts_chunk = [&](int s) {
        const int soff = 49152 + s*24576;
#pragma unroll
        for (int j = 0; j < 7; j++) {
            if (val_[j]) {
                int row = cin_[j], c4 = c4_[j];
                int a = soff + pl_[j] + row*384 + (((c4 >> 1) ^ (row & 7)) * 16) + (c4 & 1)*8;
                uint32_t h01 = pack_h2(rv[j].x, rv[j].y);
                uint32_t h23 = pack_h2(rv[j].z, rv[j].w);
                *(uint2*)(sm + a) = make_uint2(h01, h23);
            }
        }
    };

    ldg_chunk(0, db, rb, rowoff);

    for (; u < u1; u++) {
        const int ip = h & 3, hn = h >> 2, curb = b;

        int nb = b, nh = h + 1;
        if (nh == 160) { nh = 0; nb = b + 1; }
        const bool has_next = (u + 1 < u1);
        const float* ndb = depth + (size_t)nb*CHN*HW;
        const float* nrb = rgb   + (size_t)nb*CHN*HW;
        const size_t nro = (size_t)nh * 160;

        sts_chunk(0);
        ldg_chunk(1, db, rb, rowoff);

        float acc[2][5][4];
#pragma unroll
        for (int i = 0; i < 2; i++)
#pragma unroll
            for (int j = 0; j < 5; j++)
#pragma unroll
                for (int r = 0; r < 4; r++) acc[i][j][r] = 0.0f;

        const int pls = (wm == 2) ? 12288 : 0;   // this warp's source plane

        for (int c = 0; c < 8; c++) {
            __syncthreads();
            if (c + 1 < 8) sts_chunk((c + 1) & 1);
            if (c + 2 < 8)                    ldg_chunk(c + 2, db, rb, rowoff);
            else if (c == 6 && has_next)      ldg_chunk(0, ndb, nrb, nro);
            __syncthreads();

            const uint32_t xs = XB + (c & 1)*24576;
#pragma unroll
            for (int kk = 0; kk < 2; kk++) {
                uint32_t ah[2][4];
#pragma unroll
                for (int mt = 0; mt < 2; mt++) {
                    int m = wm*32 + mt*16 + (lane & 15);
                    int ca = c*4 + kk*2 + (lane >> 4);
                    uint32_t addr = su + m*512 + (ca ^ (m & 7))*16;
                    ldsm4(ah[mt], addr);
                }
                const int krow = kk*16 + (lane & 15);
                const int swz = krow & 7;
                const uint32_t rbase_a = xs + pls + krow*384;
                uint32_t bh[2][4], bh2[2];
#pragma unroll
                for (int tt = 0; tt < 2; tt++) {
                    int cc = wn*5 + tt*2 + (lane >> 4);
                    ldsm4t(bh[tt], rbase_a + (cc ^ swz)*16);
                }
                {
                    int cc = wn*5 + 4;
                    ldsm2t(bh2, rbase_a + (cc ^ swz)*16);
                }
#pragma unroll
                for (int mt = 0; mt < 2; mt++) {
#pragma unroll
                    for (int nt = 0; nt < 5; nt++) {
                        uint32_t b0, b1;
                        if (nt < 4) {
                            int g = nt >> 1, hf = nt & 1;
                            b0 = bh[g][hf*2]; b1 = bh[g][hf*2+1];
                        } else {
                            b0 = bh2[0]; b1 = bh2[1];
                        }
                        mma_f16(acc[mt][nt], ah[mt], b0, b1);
                    }
                }
            }
        }

        // ---- epilogue: stage into epi, coalesced drain ----
        __syncthreads();
#pragma unroll
        for (int mt = 0; mt < 2; mt++) {
#pragma unroll
            for (int nt = 0; nt < 5; nt++) {
                int col0 = wn*40 + nt*8 + (lane & 3)*2;
                int nw = col0 >> 2, j0 = col0 & 3;
#pragma unroll
                for (int hh = 0; hh < 2; hh++) {
                    int r = wm*32 + mt*16 + (lane >> 2) + hh*8;
                    epi[(j0*96 + r)*42 + nw]     = acc[mt][nt][hh*2]   + bias_v[mt][hh];
                    epi[((j0+1)*96 + r)*42 + nw] = acc[mt][nt][hh*2+1] + bias_v[mt][hh];
                }
            }
        }
        __syncthreads();

        for (int tk = wid; tk < 416; tk += 12) {
            if (tk < 256) {
                if (lane < 20) {
                    int rr = tk >> 2, j = tk & 3;
                    int row = (rr < 32) ? rr : rr + 32;
                    float2 v = *(const float2*)&epi[(j*96 + row)*42 + lane*2];
                    uint32_t hi = pack_h2(v.x, v.y);
                    int dd = (rr < 32) ? (rr*16 + ip*4 + j)
                                       : ((ip*4 + j)*32 + (rr - 32));
                    size_t base = ((size_t)(curb*DD + dd))*NN + hn*40 + lane*2;
                    __half* dh = (rr < 32) ? g_fq_hi : g_fk_hi;
                    *(uint32_t*)(dh + base) = hi;
                }
            } else {
                if (lane < 16) {
                    int tv = tk - 256;
                    int nw = tv >> 2, j = tv & 3;
                    float v0 = epi[(j*96 + 32 + lane*2)*42 + nw];
                    float v1 = epi[(j*96 + 33 + lane*2)*42 + nw];
                    uint32_t hi = pack_h2(v0, v1);
                    int n = hn*40 + nw;
                    size_t base = ((size_t)curb*NNP + n)*DD + (ip*4 + j)*32 + lane*2;
                    *(uint32_t*)(g_fvT_hi + base) = hi;
                }
            }
        }
        __syncthreads();   // epi region reused as x stages next unit

        b = nb; h = nh; db = ndb; rb = nrb; rowoff = nro;
    }
}

// ---------------------------------------------------------------------------
// Generic 128x64-tile mma.sync single-pass fp16 GEMM (2 CTAs/SM, 3 stages):
// (exact champion configuration)
// ---------------------------------------------------------------------------
template<int MODE>
__global__ __launch_bounds__(256, 2) void k_gemm()
{
    constexpr int K    = (MODE == 0) ? 1600 : 512;
    constexpr int LD   = (MODE == 0) ? 1600 : 512;
    constexpr int LDC  = (MODE == 0) ? 512  : 1600;
    constexpr long SA  = (MODE == 0) ? (long)DD*NN : (long)DD*DD;
    constexpr long SB  = (MODE == 0) ? (long)DD*NN : (long)NNP*DD;
    constexpr int NCH  = K / 64;

    extern __shared__ __align__(1024) char dsm[];

    const int b  = blockIdx.z;
    const int m0 = blockIdx.y * 128;
    const int n0 = blockIdx.x * 64;
    const int t    = threadIdx.x;
    const int lane = t & 31;
    const int wid  = t >> 5;
    const int wm   = wid & 3;
    const int wn   = wid >> 2;

    const uint32_t smem_u = smem_u32(dsm);

    const __half* Ahi = (MODE == 0 ? g_fq_hi : g_at_hi)  + b*SA + (long)m0*LD;
    const __half* Bhi = (MODE == 0 ? g_fk_hi : g_fvT_hi) + b*SB + (long)n0*LD;

    auto load_stage = [&](int s, int kc) {
        uint32_t base = smem_u + s*24576;
#pragma unroll
        for (int ii = 0; ii < 4; ii++) {
            int i = t + ii*256;
            int row = i >> 3, seg = i & 7;
            uint32_t off = row*128 + seg*16;
            uint32_t sw  = off ^ ((off >> 3) & 0x70);
            long go = (long)row*LD + kc;
            cpa16(base + sw, (const char*)(Ahi + go) + seg*16);
        }
#pragma unroll
        for (int ii = 0; ii < 2; ii++) {
            int i = t + ii*256;
            int row = i >> 3, seg = i & 7;
            uint32_t off = row*128 + seg*16;
            uint32_t sw  = off ^ ((off >> 3) & 0x70);
            long go = (long)row*LD + kc;
            cpa16(base + 16384 + sw, (const char*)(Bhi + go) + seg*16);
        }
        CPA_COMMIT();
    };

    float acc[2][4][4];
#pragma unroll
    for (int i = 0; i < 2; i++)
#pragma unroll
        for (int j = 0; j < 4; j++)
#pragma unroll
            for (int r = 0; r < 4; r++) acc[i][j][r] = 0.0f;

    load_stage(0, 0);
    load_stage(1, 64);
    load_stage(2, 128);   // NCH >= 8 in both modes

    const int lr = lane & 15;
    const int lc = lane >> 4;

    for (int c = 0; c < NCH; c++) {
        const int s = c - (c/3)*3;
        if (c + 2 < NCH)      asm volatile("cp.async.wait_group 2;" ::: "memory");
        else if (c + 1 < NCH) asm volatile("cp.async.wait_group 1;" ::: "memory");
        else                  asm volatile("cp.async.wait_group 0;" ::: "memory");
        __syncthreads();

        const uint32_t base = smem_u + s*24576;
#pragma unroll
        for (int kk = 0; kk < 4; kk++) {
            uint32_t a_hi[2][4];
#pragma unroll
            for (int mt = 0; mt < 2; mt++) {
                int row = wm*32 + mt*16 + lr;
                uint32_t off = row*128 + kk*32 + lc*16;
                uint32_t sw  = off ^ ((off >> 3) & 0x70);
                ldsm4(a_hi[mt], base + sw);
            }
            uint32_t b_hi[2][4];
#pragma unroll
            for (int bt = 0; bt < 2; bt++) {
                int row = wn*32 + bt*16 + lr;
                uint32_t off = row*128 + kk*32 + lc*16;
                uint32_t sw  = off ^ ((off >> 3) & 0x70);
                ldsm4(b_hi[bt], base + 16384 + sw);
            }
#pragma unroll
            for (int mt = 0; mt < 2; mt++) {
#pragma unroll
                for (int nt = 0; nt < 4; nt++) {
                    int bt = nt >> 1, hf = nt & 1;
                    mma_f16(acc[mt][nt], a_hi[mt], b_hi[bt][hf], b_hi[bt][hf+2]);
                }
            }
        }
        __syncthreads();
        if (c + 3 < NCH) load_stage(s, (c + 3)*64);
    }

    const int rq = lane >> 2;
    const int cq = (lane & 3) * 2;
#pragma unroll
    for (int mt = 0; mt < 2; mt++) {
#pragma unroll
        for (int nt = 0; nt < 4; nt++) {
            int col = n0 + wn*32 + nt*8 + cq;
            int row = m0 + wm*32 + mt*16 + rq;
            if (MODE == 0) {
                float* p0 = g_sc + (long)b*DD*DD + (long)row*LDC + col;
                *(float2*)p0            = make_float2(acc[mt][nt][0], acc[mt][nt][1]);
                *(float2*)(p0 + 8L*LDC) = make_float2(acc[mt][nt][2], acc[mt][nt][3]);
            } else {
                __half* p0 = g_oph + (long)b*DD*NN + (long)row*LDC + col;
                *(uint32_t*)p0            = pack_h2(acc[mt][nt][0], acc[mt][nt][1]);
                *(uint32_t*)(p0 + 8L*LDC) = pack_h2(acc[mt][nt][2], acc[mt][nt][3]);
            }
        }
    }
}

// ---------------------------------------------------------------------------
// K3: softmax over rows of g_sc, writes attn as single fp16 plane.
// ---------------------------------------------------------------------------
__global__ __launch_bounds__(128) void k_softmax()
{
    __shared__ float red[8];
    const size_t row = blockIdx.x;
    const float* s = g_sc + row * DD;
    const int t = threadIdx.x;

    float v0 = s[t], v1 = s[t+128], v2 = s[t+256], v3 = s[t+384];
    float m = fmaxf(fmaxf(v0, v1), fmaxf(v2, v3));
#pragma unroll
    for (int o = 16; o; o >>= 1) m = fmaxf(m, __shfl_xor_sync(0xffffffffu, m, o));
    if ((t & 31) == 0) red[t >> 5] = m;
    __syncthreads();
    m = fmaxf(fmaxf(red[0], red[1]), fmaxf(red[2], red[3]));

    const float inv = 0.04419417382415922f;  // 1/sqrt(512)
    float e0 = __expf((v0 - m) * inv);
    float e1 = __expf((v1 - m) * inv);
    float e2 = __expf((v2 - m) * inv);
    float e3 = __expf((v3 - m) * inv);
    float sum = e0 + e1 + e2 + e3;
#pragma unroll
    for (int o = 16; o; o >>= 1) sum += __shfl_xor_sync(0xffffffffu, sum, o);
    if ((t & 31) == 0) red[4 + (t >> 5)] = sum;
    __syncthreads();
    float r = 1.0f / (red[4] + red[5] + red[6] + red[7]);

    size_t base = row * DD;
    g_at_hi[base + t]       = __float2half_rn(e0 * r);
    g_at_hi[base + t + 128] = __float2half_rn(e1 * r);
    g_at_hi[base + t + 256] = __float2half_rn(e2 * r);
    g_at_hi[base + t + 384] = __float2half_rn(e3 * r);
}

// ---------------------------------------------------------------------------
// K5: PERSISTENT pixel_shuffle gather + final 1x1 conv (32 -> 256).
// SINGLE-pass fp16: Wu (1 plane) x op (1 plane). MMAs halved vs 2-pass.
// smem: Wu_hi @0 (20480); B stages @20480 + s*4096. Total 28672.
// ---------------------------------------------------------------------------
__global__ __launch_bounds__(256, 2) void k_final(
    const float* __restrict__ bu, float* __restrict__ out)
{
    extern __shared__ __align__(1024) char sm[];
    const uint32_t su = smem_u32(sm);
    const int t = threadIdx.x, lane = t & 31, wid = t >> 5;
    const int wm = wid & 3, wn = wid >> 2;
    const int rq = lane >> 2, cq = (lane & 3) * 2;

    // ---- load Wu plane once: row t at 80B pitch ----
    {
        const uint4* src_h = (const uint4*)((const char*)g_wu_hi + t*64);
#pragma unroll
        for (int c = 0; c < 4; c++)
            *(uint4*)(sm + t*80 + c*16) = src_h[c];
    }

    float bb[4][2];
#pragma unroll
    for (int mt = 0; mt < 4; mt++) {
        int ch0 = wm*64 + mt*16 + rq;
        bb[mt][0] = bu[ch0];
        bb[mt][1] = bu[ch0 + 8];
    }

    const int gc = t >> 3;
    const int ii = (t >> 2) & 1;
    const int gj = t & 3;

    const int cta = blockIdx.x;
    int u        = (3200 * cta) / 296;
    const int u1 = (3200 * (cta + 1)) / 296;

    uint4 hv;   // 8 fp16 values
    auto prefetch = [&](int uu) {
        int pb = uu / 400, r = uu - pb*400;
        int php = r / 5, pwb = r - (r/5)*5;
        int i0 = (2*php) & 3, hn = php >> 1;
        int d  = gc*16 + (i0 + ii)*4 + gj;
        hv = *(const uint4*)(g_oph + ((size_t)(pb*DD + d))*NN + hn*40 + pwb*8);
    };
    if (u < u1) prefetch(u);

    for (; u < u1; u++) {
        const int s = u & 1;
        const int b = u / 400, r = u - b*400;
        const int hp = r / 5, wblk = r - (r/5)*5;

        __syncthreads();   // stage s free; Wu visible on first iter

        // ---- stage B (already fp16; scatter into swizzled [32 c][64 px]) ----
        {
            const __half* hvals = (const __half*)&hv;
#pragma unroll
            for (int nw = 0; nw < 8; nw++) {
                int px = ii*32 + nw*4 + gj;
                uint32_t a = 20480 + s*4096 + gc*128 + (((px >> 3) ^ (gc & 7))*16) + (px & 7)*2;
                *(__half*)(sm + a) = hvals[nw];
            }
        }
        if (u + 1 < u1) prefetch(u + 1);   // overlap next gather with MMA
        __syncthreads();

        // ---- MMA (stage s): single pass Wu_hi x op ----
        float acc[4][4][4];
#pragma unroll
        for (int i = 0; i < 4; i++)
#pragma unroll
            for (int j = 0; j < 4; j++)
#pragma unroll
                for (int rr = 0; rr < 4; rr++) acc[i][j][rr] = 0.0f;

#pragma unroll
        for (int kk = 0; kk < 2; kk++) {
            uint32_t ah[4][4];
#pragma unroll
            for (int mt = 0; mt < 4; mt++) {
                int row = wm*64 + mt*16 + (lane & 15);
                uint32_t addr = su + row*80 + (kk*2 + (lane >> 4))*16;
                ldsm4(ah[mt], addr);
            }
            const int krow = kk*16 + (lane & 15);
            uint32_t bh[2][4];
#pragma unroll
            for (int tt = 0; tt < 2; tt++) {
                int cc = wn*4 + tt*2 + (lane >> 4);
                uint32_t addr = su + 20480 + s*4096 + krow*128 + ((cc ^ (krow & 7))*16);
                ldsm4t(bh[tt], addr);
            }
#pragma unroll
            for (int mt = 0; mt < 4; mt++) {
#pragma unroll
                for (int nt = 0; nt < 4; nt++) {
                    int tt = nt >> 1, hf = nt & 1;
                    mma_f16(acc[mt][nt], ah[mt], bh[tt][hf*2], bh[tt][hf*2+1]);
                }
            }
        }

        // ---- epilogue: bias + float2 stores ----
        const int h = hp*2 + wn;
#pragma unroll
        for (int mt = 0; mt < 4; mt++) {
            int ch0 = wm*64 + mt*16 + rq;
#pragma unroll
            for (int nt = 0; nt < 4; nt++) {
                int w = wblk*32 + nt*8 + cq;
                float* p0 = out + ((size_t)(b*CHN + ch0))*HW + (size_t)h*160 + w;
                *(float2*)p0          = make_float2(acc[mt][nt][0] + bb[mt][0], acc[mt][nt][1] + bb[mt][0]);
                *(float2*)(p0 + 8*HW) = make_float2(acc[mt][nt][2] + bb[mt][1], acc[mt][nt][3] + bb[mt][1]);
            }
        }
    }
}

// ---------------------------------------------------------------------------
extern "C" void kernel_launch(void* const* d_in, const int* in_sizes, int n_in,
                              void* d_out, int out_size)
{
    (void)in_sizes; (void)n_in; (void)out_size;
    const float* rgb   = (const float*)d_in[0];
    const float* depth = (const float*)d_in[1];
    const float* Wq    = (const float*)d_in[2];
    const float* bq    = (const float*)d_in[3];
    const float* Wk    = (const float*)d_in[4];
    const float* bk    = (const float*)d_in[5];
    const float* Wv    = (const float*)d_in[6];
    const float* bv    = (const float*)d_in[7];
    const float* Wu    = (const float*)d_in[8];
    const float* bu    = (const float*)d_in[9];
    float* out = (float*)d_out;

    cudaFuncSetAttribute(k_projT,   cudaFuncAttributeMaxDynamicSharedMemorySize, 114688);
    cudaFuncSetAttribute(k_gemm<0>, cudaFuncAttributeMaxDynamicSharedMemorySize, 73728);
    cudaFuncSetAttribute(k_gemm<1>, cudaFuncAttributeMaxDynamicSharedMemorySize, 73728);
    cudaFuncSetAttribute(k_final,   cudaFuncAttributeMaxDynamicSharedMemorySize, 28672);

    k_wsplit <<<96, 256>>>(Wq, Wv, Wk, Wu);
    k_projT  <<<148, 384, 114688>>>(rgb, depth, bq, bk, bv);
    k_gemm<0><<<dim3(8, 4, NB), 256, 73728>>>();
    k_softmax<<<NB*DD, 128>>>();
    k_gemm<1><<<dim3(25, 4, NB), 256, 73728>>>();
    k_final  <<<296, 256, 28672>>>(bu, out);
}

// round 17
// speedup vs baseline: 1.4040x; 1.0030x over previous
#include <cuda_runtime.h>
#include <cuda_fp16.h>
#include <cstdint>

#define NB  8
#define CHN 256
#define HW  25600
#define DD  512
#define NN  1600
#define NNP 1664

// ---------------- scratch (__device__ globals; allocation-free) ------------
__device__ float g_sc[NB*DD*DD];    // scores fp32 [d][e']
__device__ __align__(128) __half g_oph[NB*DD*NN];     // attn@V output fp16 [d][n]
__device__ __align__(128) __half g_fq_hi[NB*DD*NN];   // [d][n] single plane
__device__ __align__(128) __half g_fk_hi[NB*DD*NN];   // [e'][n] single plane
__device__ __align__(128) __half g_fvT_hi[NB*NNP*DD]; // [n][e'] single plane
__device__ __align__(128) __half g_at_hi[NB*DD*DD];   // [d][e'] single plane
__device__ __align__(128) __half g_w_hi[96*256];      // qkv weights single plane
__device__ __align__(128) __half g_wu_hi[256*32];     // Wu single fp16 plane

typedef unsigned long long u64;

// ---------------- PTX helpers (baseline ISA only) ---------------------------
__device__ __forceinline__ uint32_t smem_u32(const void* p) {
    uint32_t a;
    asm("{ .reg .u64 t; cvta.to.shared.u64 t, %1; cvt.u32.u64 %0, t; }" : "=r"(a) : "l"(p));
    return a;
}
__device__ __forceinline__ void cpa16(uint32_t s, const void* g) {
    asm volatile("cp.async.cg.shared.global [%0], [%1], 16;" :: "r"(s), "l"(g));
}
#define CPA_COMMIT() asm volatile("cp.async.commit_group;" ::: "memory")

__device__ __forceinline__ void ldsm4(uint32_t* r, uint32_t a) {
    asm volatile("ldmatrix.sync.aligned.m8n8.x4.shared.b16 {%0,%1,%2,%3}, [%4];"
        : "=r"(r[0]), "=r"(r[1]), "=r"(r[2]), "=r"(r[3]) : "r"(a));
}
__device__ __forceinline__ void ldsm4t(uint32_t* r, uint32_t a) {
    asm volatile("ldmatrix.sync.aligned.m8n8.x4.trans.shared.b16 {%0,%1,%2,%3}, [%4];"
        : "=r"(r[0]), "=r"(r[1]), "=r"(r[2]), "=r"(r[3]) : "r"(a));
}
__device__ __forceinline__ void ldsm2t(uint32_t* r, uint32_t a) {
    asm volatile("ldmatrix.sync.aligned.m8n8.x2.trans.shared.b16 {%0,%1}, [%2];"
        : "=r"(r[0]), "=r"(r[1]) : "r"(a));
}
__device__ __forceinline__ void mma_f16(float* d, const uint32_t* a, uint32_t b0, uint32_t b1) {
    asm volatile(
        "mma.sync.aligned.m16n8k16.row.col.f32.f16.f16.f32 "
        "{%0,%1,%2,%3},{%4,%5,%6,%7},{%8,%9},{%0,%1,%2,%3};"
        : "+f"(d[0]), "+f"(d[1]), "+f"(d[2]), "+f"(d[3])
        : "r"(a[0]), "r"(a[1]), "r"(a[2]), "r"(a[3]), "r"(b0), "r"(b1));
}

// pack 2 floats -> fp16x2 (lo=a, hi=b)
__device__ __forceinline__ uint32_t pack_h2(float a, float b) {
    uint32_t r;
    asm("cvt.rn.f16x2.f32 %0, %1, %2;" : "=r"(r) : "f"(b), "f"(a));
    return r;
}

// ---------------------------------------------------------------------------
// K-1: W q/v/k rows -> single fp16 plane; Wu -> single fp16 plane.
// ---------------------------------------------------------------------------
__global__ __launch_bounds__(256) void k_wsplit(
    const float* __restrict__ Wq, const float* __restrict__ Wv, const float* __restrict__ Wk,
    const float* __restrict__ Wu)
{
    int i = blockIdx.x * 256 + threadIdx.x;
    if (i < 96*256) {
        int r = i >> 8, kk = i & 255;
        float v = (r < 32) ? Wq[r*256 + kk] : ((r < 64) ? Wv[(r-32)*256 + kk] : Wk[(r-64)*256 + kk]);
        g_w_hi[i] = __float2half_rn(v);
    }
    if (i < 256*32) {
        g_wu_hi[i] = __float2half_rn(Wu[i]);
    }
}

// ---------------------------------------------------------------------------
// K1: PERSISTENT tensor-core fused q/k/v 1x1 conv + pixel_unshuffle.
// 384 threads / 12 warps (3/SMSP), warp grid 3m x 4n, warp tile 32x40.
// x: 3-stage ring, SINGLE __syncthreads per chunk (A/B-verified vs 2-sync).
// smem: W_hi @0 (48K); x slots @49152 + slot*24576 (depth @0, rgb @12288).
// epi buffer overlays slot region @49152 (64512 B). Total 122880.
// ---------------------------------------------------------------------------
__global__ __launch_bounds__(384, 1) void k_projT(
    const float* __restrict__ rgb, const float* __restrict__ depth,
    const float* __restrict__ bq, const float* __restrict__ bk,
    const float* __restrict__ bv)
{
    extern __shared__ __align__(1024) char sm[];
    const int t = threadIdx.x, lane = t & 31, wid = t >> 5;
    const int wn = wid & 3, wm = wid >> 2;       // wm 0..2, wn 0..3
    const uint32_t su = smem_u32(sm);
    const uint32_t XB = su + 49152;
    float* const epi = (float*)(sm + 49152);

    // ---- W plane into smem (once per CTA) ----
    for (int i = t; i < 96*32; i += 384) {
        int m = i >> 5, c = i & 31;
        uint4 v1 = *(const uint4*)((const char*)g_w_hi + m*512 + c*16);
        int sw = (c ^ (m & 7)) * 16;
        *(uint4*)(sm + m*512 + sw) = v1;
    }

    float bias_v[2][2];
#pragma unroll
    for (int mt = 0; mt < 2; mt++)
#pragma unroll
        for (int hh = 0; hh < 2; hh++) {
            int r = wm*32 + mt*16 + (lane >> 2) + hh*8;
            bias_v[mt][hh] = (r < 32) ? bq[r] : ((r < 64) ? bv[r-32] : bk[r-64]);
        }

    // per-thread ldg mapping: 2560 float4 items (src x 32 cin x 40 c4)
    int cin_[7], c4_[7], pl_[7];
    bool val_[7];
#pragma unroll
    for (int j = 0; j < 7; j++) {
        int item = t + j*384;
        val_[j] = item < 2560;
        int it2 = val_[j] ? item : 0;
        int src = (it2 >= 1280) ? 1 : 0;
        int rem = it2 - src*1280;
        cin_[j] = rem / 40; c4_[j] = rem % 40;
        pl_[j]  = src ? 12288 : 0;
    }
    __syncthreads();

    const int cta = blockIdx.x;
    int u        = (1280 * cta) / 148;
    const int u1 = (1280 * (cta + 1)) / 148;

    int b = u / 160, h = u - b*160;
    const float* db = depth + (size_t)b*CHN*HW;
    const float* rb = rgb   + (size_t)b*CHN*HW;
    size_t rowoff = (size_t)h * 160;

    float4 rv[7];
    auto ldg_chunk = [&](int c, const float* dB, const float* rB, size_t ro) {
#pragma unroll
        for (int j = 0; j < 7; j++) {
            if (val_[j]) {
                const float* bp = pl_[j] ? rB : dB;
                rv[j] = *(const float4*)(bp + (size_t)(c*32 + cin_[j])*HW + ro + c4_[j]*4);
            }
        }
    };
    auto sts_chunk = [&](int slot) {
        const int soff = 49152 + slot*24576;
#pragma unroll
        for (int j = 0; j < 7; j++) {
            if (val_[j]) {
                int row = cin_[j], c4 = c4_[j];
                int a = soff + pl_[j] + row*384 + (((c4 >> 1) ^ (row & 7)) * 16) + (c4 & 1)*8;
                uint32_t h01 = pack_h2(rv[j].x, rv[j].y);
                uint32_t h23 = pack_h2(rv[j].z, rv[j].w);
                *(uint2*)(sm + a) = make_uint2(h01, h23);
            }
        }
    };

    ldg_chunk(0, db, rb, rowoff);

    for (; u < u1; u++) {
        const int ip = h & 3, hn = h >> 2, curb = b;

        int nb = b, nh = h + 1;
        if (nh == 160) { nh = 0; nb = b + 1; }
        const bool has_next = (u + 1 < u1);
        const float* ndb = depth + (size_t)nb*CHN*HW;
        const float* nrb = rgb   + (size_t)nb*CHN*HW;
        const size_t nro = (size_t)nh * 160;

        sts_chunk(0);                 // chunk 0 -> slot 0
        ldg_chunk(1, db, rb, rowoff);

        float acc[2][5][4];
#pragma unroll
        for (int i = 0; i < 2; i++)
#pragma unroll
            for (int j = 0; j < 5; j++)
#pragma unroll
                for (int r = 0; r < 4; r++) acc[i][j][r] = 0.0f;

        const int pls = (wm == 2) ? 12288 : 0;   // this warp's source plane

        for (int c = 0; c < 8; c++) {
            __syncthreads();          // slot c%3 visible; slot (c+1)%3 free
            if (c < 7) {
                int ns = c + 1 - ((c + 1)/3)*3;
                sts_chunk(ns);        // chunk c+1 -> slot (c+1)%3
            }
            if (c < 6)                       ldg_chunk(c + 2, db, rb, rowoff);
            else if (c == 6 && has_next)     ldg_chunk(0, ndb, nrb, nro);

            const int slot = c - (c/3)*3;
            const uint32_t xs = XB + slot*24576;
#pragma unroll
            for (int kk = 0; kk < 2; kk++) {
                uint32_t ah[2][4];
#pragma unroll
                for (int mt = 0; mt < 2; mt++) {
                    int m = wm*32 + mt*16 + (lane & 15);
                    int ca = c*4 + kk*2 + (lane >> 4);
                    uint32_t addr = su + m*512 + (ca ^ (m & 7))*16;
                    ldsm4(ah[mt], addr);
                }
                const int krow = kk*16 + (lane & 15);
                const int swz = krow & 7;
                const uint32_t rbase_a = xs + pls + krow*384;
                uint32_t bh[2][4], bh2[2];
#pragma unroll
                for (int tt = 0; tt < 2; tt++) {
                    int cc = wn*5 + tt*2 + (lane >> 4);
                    ldsm4t(bh[tt], rbase_a + (cc ^ swz)*16);
                }
                {
                    int cc = wn*5 + 4;
                    ldsm2t(bh2, rbase_a + (cc ^ swz)*16);
                }
#pragma unroll
                for (int mt = 0; mt < 2; mt++) {
#pragma unroll
                    for (int nt = 0; nt < 5; nt++) {
                        uint32_t b0, b1;
                        if (nt < 4) {
                            int g = nt >> 1, hf = nt & 1;
                            b0 = bh[g][hf*2]; b1 = bh[g][hf*2+1];
                        } else {
                            b0 = bh2[0]; b1 = bh2[1];
                        }
                        mma_f16(acc[mt][nt], ah[mt], b0, b1);
                    }
                }
            }
        }

        // ---- epilogue: stage into epi, coalesced drain ----
        __syncthreads();
#pragma unroll
        for (int mt = 0; mt < 2; mt++) {
#pragma unroll
            for (int nt = 0; nt < 5; nt++) {
                int col0 = wn*40 + nt*8 + (lane & 3)*2;
                int nw = col0 >> 2, j0 = col0 & 3;
#pragma unroll
                for (int hh = 0; hh < 2; hh++) {
                    int r = wm*32 + mt*16 + (lane >> 2) + hh*8;
                    epi[(j0*96 + r)*42 + nw]     = acc[mt][nt][hh*2]   + bias_v[mt][hh];
                    epi[((j0+1)*96 + r)*42 + nw] = acc[mt][nt][hh*2+1] + bias_v[mt][hh];
                }
            }
        }
        __syncthreads();

        for (int tk = wid; tk < 416; tk += 12) {
            if (tk < 256) {
                if (lane < 20) {
                    int rr = tk >> 2, j = tk & 3;
                    int row = (rr < 32) ? rr : rr + 32;
                    float2 v = *(const float2*)&epi[(j*96 + row)*42 + lane*2];
                    uint32_t hi = pack_h2(v.x, v.y);
                    int dd = (rr < 32) ? (rr*16 + ip*4 + j)
                                       : ((ip*4 + j)*32 + (rr - 32));
                    size_t base = ((size_t)(curb*DD + dd))*NN + hn*40 + lane*2;
                    __half* dh = (rr < 32) ? g_fq_hi : g_fk_hi;
                    *(uint32_t*)(dh + base) = hi;
                }
            } else {
                if (lane < 16) {
                    int tv = tk - 256;
                    int nw = tv >> 2, j = tv & 3;
                    float v0 = epi[(j*96 + 32 + lane*2)*42 + nw];
                    float v1 = epi[(j*96 + 33 + lane*2)*42 + nw];
                    uint32_t hi = pack_h2(v0, v1);
                    int n = hn*40 + nw;
                    size_t base = ((size_t)curb*NNP + n)*DD + (ip*4 + j)*32 + lane*2;
                    *(uint32_t*)(g_fvT_hi + base) = hi;
                }
            }
        }
        __syncthreads();   // epi region reused as x slots next unit

        b = nb; h = nh; db = ndb; rb = nrb; rowoff = nro;
    }
}

// ---------------------------------------------------------------------------
// Generic 128x64-tile mma.sync single-pass fp16 GEMM (2 CTAs/SM, 3 stages):
// (exact champion configuration)
// ---------------------------------------------------------------------------
template<int MODE>
__global__ __launch_bounds__(256, 2) void k_gemm()
{
    constexpr int K    = (MODE == 0) ? 1600 : 512;
    constexpr int LD   = (MODE == 0) ? 1600 : 512;
    constexpr int LDC  = (MODE == 0) ? 512  : 1600;
    constexpr long SA  = (MODE == 0) ? (long)DD*NN : (long)DD*DD;
    constexpr long SB  = (MODE == 0) ? (long)DD*NN : (long)NNP*DD;
    constexpr int NCH  = K / 64;

    extern __shared__ __align__(1024) char dsm[];

    const int b  = blockIdx.z;
    const int m0 = blockIdx.y * 128;
    const int n0 = blockIdx.x * 64;
    const int t    = threadIdx.x;
    const int lane = t & 31;
    const int wid  = t >> 5;
    const int wm   = wid & 3;
    const int wn   = wid >> 2;

    const uint32_t smem_u = smem_u32(dsm);

    const __half* Ahi = (MODE == 0 ? g_fq_hi : g_at_hi)  + b*SA + (long)m0*LD;
    const __half* Bhi = (MODE == 0 ? g_fk_hi : g_fvT_hi) + b*SB + (long)n0*LD;

    auto load_stage = [&](int s, int kc) {
        uint32_t base = smem_u + s*24576;
#pragma unroll
        for (int ii = 0; ii < 4; ii++) {
            int i = t + ii*256;
            int row = i >> 3, seg = i & 7;
            uint32_t off = row*128 + seg*16;
            uint32_t sw  = off ^ ((off >> 3) & 0x70);
            long go = (long)row*LD + kc;
            cpa16(base + sw, (const char*)(Ahi + go) + seg*16);
        }
#pragma unroll
        for (int ii = 0; ii < 2; ii++) {
            int i = t + ii*256;
            int row = i >> 3, seg = i & 7;
            uint32_t off = row*128 + seg*16;
            uint32_t sw  = off ^ ((off >> 3) & 0x70);
            long go = (long)row*LD + kc;
            cpa16(base + 16384 + sw, (const char*)(Bhi + go) + seg*16);
        }
        CPA_COMMIT();
    };

    float acc[2][4][4];
#pragma unroll
    for (int i = 0; i < 2; i++)
#pragma unroll
        for (int j = 0; j < 4; j++)
#pragma unroll
            for (int r = 0; r < 4; r++) acc[i][j][r] = 0.0f;

    load_stage(0, 0);
    load_stage(1, 64);
    load_stage(2, 128);   // NCH >= 8 in both modes

    const int lr = lane & 15;
    const int lc = lane >> 4;

    for (int c = 0; c < NCH; c++) {
        const int s = c - (c/3)*3;
        if (c + 2 < NCH)      asm volatile("cp.async.wait_group 2;" ::: "memory");
        else if (c + 1 < NCH) asm volatile("cp.async.wait_group 1;" ::: "memory");
        else                  asm volatile("cp.async.wait_group 0;" ::: "memory");
        __syncthreads();

        const uint32_t base = smem_u + s*24576;
#pragma unroll
        for (int kk = 0; kk < 4; kk++) {
            uint32_t a_hi[2][4];
#pragma unroll
            for (int mt = 0; mt < 2; mt++) {
                int row = wm*32 + mt*16 + lr;
                uint32_t off = row*128 + kk*32 + lc*16;
                uint32_t sw  = off ^ ((off >> 3) & 0x70);
                ldsm4(a_hi[mt], base + sw);
            }
            uint32_t b_hi[2][4];
#pragma unroll
            for (int bt = 0; bt < 2; bt++) {
                int row = wn*32 + bt*16 + lr;
                uint32_t off = row*128 + kk*32 + lc*16;
                uint32_t sw  = off ^ ((off >> 3) & 0x70);
                ldsm4(b_hi[bt], base + 16384 + sw);
            }
#pragma unroll
            for (int mt = 0; mt < 2; mt++) {
#pragma unroll
                for (int nt = 0; nt < 4; nt++) {
                    int bt = nt >> 1, hf = nt & 1;
                    mma_f16(acc[mt][nt], a_hi[mt], b_hi[bt][hf], b_hi[bt][hf+2]);
                }
            }
        }
        __syncthreads();
        if (c + 3 < NCH) load_stage(s, (c + 3)*64);
    }

    const int rq = lane >> 2;
    const int cq = (lane & 3) * 2;
#pragma unroll
    for (int mt = 0; mt < 2; mt++) {
#pragma unroll
        for (int nt = 0; nt < 4; nt++) {
            int col = n0 + wn*32 + nt*8 + cq;
            int row = m0 + wm*32 + mt*16 + rq;
            if (MODE == 0) {
                float* p0 = g_sc + (long)b*DD*DD + (long)row*LDC + col;
                *(float2*)p0            = make_float2(acc[mt][nt][0], acc[mt][nt][1]);
                *(float2*)(p0 + 8L*LDC) = make_float2(acc[mt][nt][2], acc[mt][nt][3]);
            } else {
                __half* p0 = g_oph + (long)b*DD*NN + (long)row*LDC + col;
                *(uint32_t*)p0            = pack_h2(acc[mt][nt][0], acc[mt][nt][1]);
                *(uint32_t*)(p0 + 8L*LDC) = pack_h2(acc[mt][nt][2], acc[mt][nt][3]);
            }
        }
    }
}

// ---------------------------------------------------------------------------
// K3: softmax over rows of g_sc (float4 loads), writes attn fp16 plane.
// ---------------------------------------------------------------------------
__global__ __launch_bounds__(128) void k_softmax()
{
    __shared__ float red[8];
    const size_t row = blockIdx.x;
    const float* s = g_sc + row * DD;
    const int t = threadIdx.x;

    float4 v = *(const float4*)(s + t*4);
    float m = fmaxf(fmaxf(v.x, v.y), fmaxf(v.z, v.w));
#pragma unroll
    for (int o = 16; o; o >>= 1) m = fmaxf(m, __shfl_xor_sync(0xffffffffu, m, o));
    if ((t & 31) == 0) red[t >> 5] = m;
    __syncthreads();
    m = fmaxf(fmaxf(red[0], red[1]), fmaxf(red[2], red[3]));

    const float inv = 0.04419417382415922f;  // 1/sqrt(512)
    float e0 = __expf((v.x - m) * inv);
    float e1 = __expf((v.y - m) * inv);
    float e2 = __expf((v.z - m) * inv);
    float e3 = __expf((v.w - m) * inv);
    float sum = e0 + e1 + e2 + e3;
#pragma unroll
    for (int o = 16; o; o >>= 1) sum += __shfl_xor_sync(0xffffffffu, sum, o);
    if ((t & 31) == 0) red[4 + (t >> 5)] = sum;
    __syncthreads();
    float r = 1.0f / (red[4] + red[5] + red[6] + red[7]);

    uint2 hv = make_uint2(pack_h2(e0 * r, e1 * r), pack_h2(e2 * r, e3 * r));
    *(uint2*)(g_at_hi + row * DD + t*4) = hv;
}

// ---------------------------------------------------------------------------
// K5: PERSISTENT pixel_shuffle gather + final 1x1 conv (32 -> 256).
// SINGLE-pass fp16 (exact champion version).
// ---------------------------------------------------------------------------
__global__ __launch_bounds__(256, 2) void k_final(
    const float* __restrict__ bu, float* __restrict__ out)
{
    extern __shared__ __align__(1024) char sm[];
    const uint32_t su = smem_u32(sm);
    const int t = threadIdx.x, lane = t & 31, wid = t >> 5;
    const int wm = wid & 3, wn = wid >> 2;
    const int rq = lane >> 2, cq = (lane & 3) * 2;

    // ---- load Wu plane once: row t at 80B pitch ----
    {
        const uint4* src_h = (const uint4*)((const char*)g_wu_hi + t*64);
#pragma unroll
        for (int c = 0; c < 4; c++)
            *(uint4*)(sm + t*80 + c*16) = src_h[c];
    }

    float bb[4][2];
#pragma unroll
    for (int mt = 0; mt < 4; mt++) {
        int ch0 = wm*64 + mt*16 + rq;
        bb[mt][0] = bu[ch0];
        bb[mt][1] = bu[ch0 + 8];
    }

    const int gc = t >> 3;
    const int ii = (t >> 2) & 1;
    const int gj = t & 3;

    const int cta = blockIdx.x;
    int u        = (3200 * cta) / 296;
    const int u1 = (3200 * (cta + 1)) / 296;

    uint4 hv;   // 8 fp16 values
    auto prefetch = [&](int uu) {
        int pb = uu / 400, r = uu - pb*400;
        int php = r / 5, pwb = r - (r/5)*5;
        int i0 = (2*php) & 3, hn = php >> 1;
        int d  = gc*16 + (i0 + ii)*4 + gj;
        hv = *(const uint4*)(g_oph + ((size_t)(pb*DD + d))*NN + hn*40 + pwb*8);
    };
    if (u < u1) prefetch(u);

    for (; u < u1; u++) {
        const int s = u & 1;
        const int b = u / 400, r = u - b*400;
        const int hp = r / 5, wblk = r - (r/5)*5;

        __syncthreads();   // stage s free; Wu visible on first iter

        {
            const __half* hvals = (const __half*)&hv;
#pragma unroll
            for (int nw = 0; nw < 8; nw++) {
                int px = ii*32 + nw*4 + gj;
                uint32_t a = 20480 + s*4096 + gc*128 + (((px >> 3) ^ (gc & 7))*16) + (px & 7)*2;
                *(__half*)(sm + a) = hvals[nw];
            }
        }
        if (u + 1 < u1) prefetch(u + 1);
        __syncthreads();

        float acc[4][4][4];
#pragma unroll
        for (int i = 0; i < 4; i++)
#pragma unroll
            for (int j = 0; j < 4; j++)
#pragma unroll
                for (int rr = 0; rr < 4; rr++) acc[i][j][rr] = 0.0f;

#pragma unroll
        for (int kk = 0; kk < 2; kk++) {
            uint32_t ah[4][4];
#pragma unroll
            for (int mt = 0; mt < 4; mt++) {
                int row = wm*64 + mt*16 + (lane & 15);
                uint32_t addr = su + row*80 + (kk*2 + (lane >> 4))*16;
                ldsm4(ah[mt], addr);
            }
            const int krow = kk*16 + (lane & 15);
            uint32_t bh[2][4];
#pragma unroll
            for (int tt = 0; tt < 2; tt++) {
                int cc = wn*4 + tt*2 + (lane >> 4);
                uint32_t addr = su + 20480 + s*4096 + krow*128 + ((cc ^ (krow & 7))*16);
                ldsm4t(bh[tt], addr);
            }
#pragma unroll
            for (int mt = 0; mt < 4; mt++) {
#pragma unroll
                for (int nt = 0; nt < 4; nt++) {
                    int tt = nt >> 1, hf = nt & 1;
                    mma_f16(acc[mt][nt], ah[mt], bh[tt][hf*2], bh[tt][hf*2+1]);
                }
            }
        }

        const int h = hp*2 + wn;
#pragma unroll
        for (int mt = 0; mt < 4; mt++) {
            int ch0 = wm*64 + mt*16 + rq;
#pragma unroll
            for (int nt = 0; nt < 4; nt++) {
                int w = wblk*32 + nt*8 + cq;
                float* p0 = out + ((size_t)(b*CHN + ch0))*HW + (size_t)h*160 + w;
                *(float2*)p0          = make_float2(acc[mt][nt][0] + bb[mt][0], acc[mt][nt][1] + bb[mt][0]);
                *(float2*)(p0 + 8*HW) = make_float2(acc[mt][nt][2] + bb[mt][1], acc[mt][nt][3] + bb[mt][1]);
            }
        }
    }
}

// ---------------------------------------------------------------------------
extern "C" void kernel_launch(void* const* d_in, const int* in_sizes, int n_in,
                              void* d_out, int out_size)
{
    (void)in_sizes; (void)n_in; (void)out_size;
    const float* rgb   = (const float*)d_in[0];
    const float* depth = (const float*)d_in[1];
    const float* Wq    = (const float*)d_in[2];
    const float* bq    = (const float*)d_in[3];
    const float* Wk    = (const float*)d_in[4];
    const float* bk    = (const float*)d_in[5];
    const float* Wv    = (const float*)d_in[6];
    const float* bv    = (const float*)d_in[7];
    const float* Wu    = (const float*)d_in[8];
    const float* bu    = (const float*)d_in[9];
    float* out = (float*)d_out;

    cudaFuncSetAttribute(k_projT,   cudaFuncAttributeMaxDynamicSharedMemorySize, 122880);
    cudaFuncSetAttribute(k_gemm<0>, cudaFuncAttributeMaxDynamicSharedMemorySize, 73728);
    cudaFuncSetAttribute(k_gemm<1>, cudaFuncAttributeMaxDynamicSharedMemorySize, 73728);
    cudaFuncSetAttribute(k_final,   cudaFuncAttributeMaxDynamicSharedMemorySize, 28672);

    k_wsplit <<<96, 256>>>(Wq, Wv, Wk, Wu);
    k_projT  <<<148, 384, 122880>>>(rgb, depth, bq, bk, bv);
    k_gemm<0><<<dim3(8, 4, NB), 256, 73728>>>();
    k_softmax<<<NB*DD, 128>>>();
    k_gemm<1><<<dim3(25, 4, NB), 256, 73728>>>();
    k_final  <<<296, 256, 28672>>>(bu, out);
}